// round 4
// baseline (speedup 1.0000x reference)
#include <cuda_runtime.h>

// Problem constants
#define NB 4
#define CC 128
#define HH 64
#define WW 64
#define HW 4096       // 64*64
#define RKT 21        // 7*3 taps
#define MM (CC*RKT)   // 2688

// scratch: t6[n, m, d]  (4 * 2688 * 128 floats = 5.5 MB)
__device__ float g_t6[NB * MM * CC];

// ---- packed f32x2 helpers (sm_103a FFMA2 path, see SASS_QUICKREF) ----------
__device__ __forceinline__ unsigned long long pack_dup(float a) {
    unsigned long long r;
    asm("mov.b64 %0, {%1, %1};" : "=l"(r) : "f"(a));
    return r;
}
__device__ __forceinline__ void fma2(unsigned long long& acc,
                                     unsigned long long a,
                                     unsigned long long b) {
    asm("fma.rn.f32x2 %0, %1, %2, %0;" : "+l"(acc) : "l"(a), "l"(b));
}
__device__ __forceinline__ void unpack2(unsigned long long v, float& lo, float& hi) {
    asm("mov.b64 {%0, %1}, %2;" : "=f"(lo), "=f"(hi) : "l"(v));
}

// ---------------------------------------------------------------------------
// Kernel 1:  t6[n,m,d] = p6w[m,d] * (1/64) * sum_hw A[n,m,hw] * x[n,d,hw]
//   A[n,m,hw] = x[n, c, h+dr, w+dk]  (zero outside), m = c*21 + rk
// GEMM per n: M=2688 (tile 32), N=128 (full), K=4096 (tile 32)
// ---------------------------------------------------------------------------
__global__ __launch_bounds__(256) void k1_corr(const float* __restrict__ x,
                                               const float* __restrict__ p6w)
{
    const int n  = blockIdx.y;
    const int m0 = blockIdx.x * 32;
    const int t  = threadIdx.x;
    const int tm = t >> 5;    // 0..7  (m micro-group)
    const int tn = t & 31;    // 0..31 (d micro-group)

    __shared__ float As[32][33];    // [kk][mi], padded
    __shared__ float Bs[32][128];   // [kk][d]
    __shared__ int s_c[32], s_dr[32], s_dk[32];

    if (t < 32) {
        int m  = m0 + t;
        int c  = m / RKT;
        int rk = m - c * RKT;
        s_c[t]  = c;
        s_dr[t] = 3 * (rk / 3) - 9;
        s_dk[t] = 2 * (rk % 3) - 2;
    }
    __syncthreads();

    // acc2[j][p]: m-row j (of 4), p selects d-pair {4tn+2p, 4tn+2p+1}
    unsigned long long acc2[4][2] = {};
    const float* xn = x + (size_t)n * CC * HW;

    #pragma unroll 1
    for (int kc = 0; kc < HW / 32; kc++) {
        const int h  = kc >> 1;          // row of this K-chunk
        const int w0 = (kc & 1) << 5;    // 0 or 32

        // gather A tile: 1024 elems, 4 per thread, coalesced over kk (=w)
        #pragma unroll
        for (int i = 0; i < 4; i++) {
            int idx = i * 256 + t;
            int kk  = idx & 31;
            int mi  = idx >> 5;
            int hh  = h + s_dr[mi];
            int ww  = w0 + kk + s_dk[mi];
            float v = 0.0f;
            if ((unsigned)hh < 64u && (unsigned)ww < 64u)
                v = xn[s_c[mi] * HW + (hh << 6) + ww];
            As[kk][mi] = v;
        }
        // load B tile: x[n,d,hw0+kk] for all d, 16 per thread, coalesced
        {
            int kk = t & 31;
            int hw = (kc << 5) + kk;
            int db = t >> 5;
            #pragma unroll
            for (int j = 0; j < 16; j++)
                Bs[kk][db + (j << 3)] = xn[(db + (j << 3)) * HW + hw];
        }
        __syncthreads();

        #pragma unroll
        for (int kk = 0; kk < 32; kk++) {
            ulonglong2 b2 = *(const ulonglong2*)&Bs[kk][tn << 2];
            #pragma unroll
            for (int j = 0; j < 4; j++) {
                unsigned long long a2 = pack_dup(As[kk][(tm << 2) + j]);
                fma2(acc2[j][0], a2, b2.x);
                fma2(acc2[j][1], a2, b2.y);
            }
        }
        __syncthreads();
    }

    // epilogue: t6 = p6w * t3,  t3 = acc / 64
    const float s1 = 1.0f / 64.0f;
    #pragma unroll
    for (int j = 0; j < 4; j++) {
        int m = m0 + (tm << 2) + j;
        int d = tn << 2;
        float4 p = *(const float4*)&p6w[m * CC + d];
        float a0, a1, a2v, a3;
        unpack2(acc2[j][0], a0, a1);
        unpack2(acc2[j][1], a2v, a3);
        float4 o;
        o.x = p.x * (a0  * s1);
        o.y = p.y * (a1  * s1);
        o.z = p.z * (a2v * s1);
        o.w = p.w * (a3  * s1);
        *(float4*)&g_t6[((size_t)n * MM + m) * CC + d] = o;
    }
}

// ---------------------------------------------------------------------------
// Kernel 2:  out[n,d,hw] = (1/sqrt(2688)) * sum_m (p5w[m,hw]+1)*A[n,m,hw] * t6[n,m,d]
// GEMM per n: M=4096 (hw, tile 32), N=128 (full), K=2688 (tile 32)
// ---------------------------------------------------------------------------
__global__ __launch_bounds__(256) void k2_proj(const float* __restrict__ x,
                                               const float* __restrict__ p5w,
                                               float* __restrict__ out)
{
    const int n   = blockIdx.y;
    const int hw0 = blockIdx.x * 32;
    const int h   = hw0 >> 6;          // fixed row for this block
    const int w0  = hw0 & 63;          // 0 or 32
    const int t   = threadIdx.x;
    const int tm  = t >> 5;            // hw micro-group
    const int tn  = t & 31;            // d micro-group

    __shared__ float Ts[32][33];       // [kk(m)][hwi], padded
    __shared__ float T6s[32][128];     // [kk][d]

    unsigned long long acc2[4][2] = {};
    const float* xn  = x + (size_t)n * CC * HW;
    const float* t6n = g_t6 + (size_t)n * MM * CC;

    #pragma unroll 1
    for (int mc = 0; mc < MM / 32; mc++) {
        const int mb = mc * 32;

        // gather T7 tile: (p5+1) * shifted x, 4 per thread, coalesced over hwi
        #pragma unroll
        for (int i = 0; i < 4; i++) {
            int idx = i * 256 + t;
            int hwi = idx & 31;
            int kk  = idx >> 5;
            int m   = mb + kk;
            int c   = m / RKT;
            int rk  = m - c * RKT;
            int hh  = h + 3 * (rk / 3) - 9;
            int ww  = w0 + hwi + 2 * (rk % 3) - 2;
            float v = 0.0f;
            if ((unsigned)hh < 64u && (unsigned)ww < 64u)
                v = xn[c * HW + (hh << 6) + ww];
            float p = p5w[(size_t)m * HW + hw0 + hwi];
            Ts[kk][hwi] = (p + 1.0f) * v;
        }
        // load t6 tile: 4096 elems, 16 per thread, coalesced
        #pragma unroll
        for (int i = 0; i < 16; i++) {
            int idx = i * 256 + t;
            int kk  = idx >> 7;
            int d   = idx & 127;
            T6s[kk][d] = t6n[(mb + kk) * CC + d];
        }
        __syncthreads();

        #pragma unroll
        for (int kk = 0; kk < 32; kk++) {
            ulonglong2 b2 = *(const ulonglong2*)&T6s[kk][tn << 2];
            #pragma unroll
            for (int j = 0; j < 4; j++) {
                unsigned long long a2 = pack_dup(Ts[kk][(tm << 2) + j]);
                fma2(acc2[j][0], a2, b2.x);
                fma2(acc2[j][1], a2, b2.y);
            }
        }
        __syncthreads();
    }

    // epilogue: out[(n*C + d)*HW + hw], float4 along hw
    // acc2[j][p] holds hw-row (tm*4+j), d-pair {4tn+2p, 4tn+2p+1}
    const float s2 = 1.0f / sqrtf((float)MM);   // 1/sqrt(2688)
    float accf[4][4];
    #pragma unroll
    for (int j = 0; j < 4; j++) {
        unpack2(acc2[j][0], accf[j][0], accf[j][1]);
        unpack2(acc2[j][1], accf[j][2], accf[j][3]);
    }
    const int hwb = hw0 + (tm << 2);
    #pragma unroll
    for (int jj = 0; jj < 4; jj++) {
        int d = (tn << 2) + jj;
        float4 o;
        o.x = accf[0][jj] * s2;
        o.y = accf[1][jj] * s2;
        o.z = accf[2][jj] * s2;
        o.w = accf[3][jj] * s2;
        *(float4*)&out[((size_t)n * CC + d) * HW + hwb] = o;
    }
}

extern "C" void kernel_launch(void* const* d_in, const int* in_sizes, int n_in,
                              void* d_out, int out_size)
{
    const float* x   = (const float*)d_in[0];   // (4,128,64,64)
    const float* p5w = (const float*)d_in[1];   // (1,128,7,3,64,64)
    const float* p6w = (const float*)d_in[2];   // (1,128,7,3,128)
    float* out = (float*)d_out;                 // (4,128,64,64)

    k1_corr<<<dim3(MM / 32, NB), 256>>>(x, p6w);
    k2_proj<<<dim3(HW / 32, NB), 256>>>(x, p5w, out);
}

// round 6
// speedup vs baseline: 1.3741x; 1.3741x over previous
#include <cuda_runtime.h>

// Problem constants
#define NB 4
#define CC 128
#define HW 4096       // 64*64
#define RKT 21        // 7*3 taps
#define MM (CC*RKT)   // 2688

// scratch: t6[n, m, d]  (4 * 2688 * 128 floats = 5.5 MB)
__device__ float g_t6[NB * MM * CC];

// ---- packed f32x2 helpers (sm_103a FFMA2 path) -----------------------------
__device__ __forceinline__ unsigned long long pack_dup(float a) {
    unsigned long long r;
    asm("mov.b64 %0, {%1, %1};" : "=l"(r) : "f"(a));
    return r;
}
__device__ __forceinline__ void fma2(unsigned long long& acc,
                                     unsigned long long a,
                                     unsigned long long b) {
    asm("fma.rn.f32x2 %0, %1, %2, %0;" : "+l"(acc) : "l"(a), "l"(b));
}
__device__ __forceinline__ void unpack2(unsigned long long v, float& lo, float& hi) {
    asm("mov.b64 {%0, %1}, %2;" : "=f"(lo), "=f"(hi) : "l"(v));
}

// Tile geometry (both kernels): block = 128 threads, tile = 32(M) x 128(d), BK=32
// micro-tile per thread: 4 M-rows x 8 d-cols (4 f32x2 pairs) = 16 FFMA2 / kk
#define AS_STRIDE 36    // 32 + 4 pad
#define BS_STRIDE 132   // 128 + 4 pad

// ---------------------------------------------------------------------------
// Kernel 1:  t6[n,m,d] = p6w[m,d] * (1/64) * sum_hw A[n,m,hw] * x[n,d,hw]
//   A[n,m,hw] = x[n, c, h+dr, w+dk]  (zero outside), m = c*21 + rk
// GEMM per n: M=2688 (tile 32), N=128 (full), K=4096 (BK 32)
// ---------------------------------------------------------------------------
__global__ __launch_bounds__(128) void k1_corr(const float* __restrict__ x,
                                               const float* __restrict__ p6w)
{
    const int n  = blockIdx.y;
    const int m0 = blockIdx.x * 32;
    const int t  = threadIdx.x;
    const int tm = t >> 4;    // 0..7  -> m rows tm*4..+3
    const int tn = t & 15;    // 0..15 -> d cols tn*8..+7

    __shared__ float As[32][AS_STRIDE];   // [kk][mi]
    __shared__ float Bs[32][BS_STRIDE];   // [kk][d]
    __shared__ int s_c[32], s_dr[32], s_dk[32];

    if (t < 32) {
        int m  = m0 + t;
        int c  = m / RKT;
        int rk = m - c * RKT;
        s_c[t]  = c;
        s_dr[t] = 3 * (rk / 3) - 9;
        s_dk[t] = 2 * (rk % 3) - 2;
    }
    __syncthreads();

    unsigned long long acc2[4][4] = {};   // [m-row j][d-pair p]
    const float* xn = x + (size_t)n * CC * HW;

    const int lkk = t & 31;   // lane's kk for gathers
    const int lg  = t >> 5;   // 0..3

    #pragma unroll 1
    for (int kc = 0; kc < HW / 32; kc++) {
        const int h  = kc >> 1;
        const int w0 = (kc & 1) << 5;

        // gather A tile: 32m x 32kk, 8 elems/thread, coalesced over kk(=w)
        #pragma unroll
        for (int i = 0; i < 8; i++) {
            int mi = i * 4 + lg;
            int hh = h + s_dr[mi];
            int ww = w0 + lkk + s_dk[mi];
            float v = 0.0f;
            if ((unsigned)hh < 64u && (unsigned)ww < 64u)
                v = xn[s_c[mi] * HW + (hh << 6) + ww];
            As[lkk][mi] = v;
        }
        // load B tile: x[n,d,kc*32+kk] for all 128 d, 32 elems/thread
        {
            int hw = (kc << 5) + lkk;
            #pragma unroll
            for (int j = 0; j < 32; j++) {
                int d = lg + (j << 2);
                Bs[lkk][d] = xn[d * HW + hw];
            }
        }
        __syncthreads();

        #pragma unroll 16
        for (int kk = 0; kk < 32; kk++) {
            float4 a4 = *(const float4*)&As[kk][tm << 2];
            ulonglong2 b01 = *(const ulonglong2*)&Bs[kk][tn << 3];
            ulonglong2 b23 = *(const ulonglong2*)&Bs[kk][(tn << 3) + 4];
            unsigned long long a0 = pack_dup(a4.x);
            unsigned long long a1 = pack_dup(a4.y);
            unsigned long long a2 = pack_dup(a4.z);
            unsigned long long a3 = pack_dup(a4.w);
            fma2(acc2[0][0], a0, b01.x); fma2(acc2[0][1], a0, b01.y);
            fma2(acc2[0][2], a0, b23.x); fma2(acc2[0][3], a0, b23.y);
            fma2(acc2[1][0], a1, b01.x); fma2(acc2[1][1], a1, b01.y);
            fma2(acc2[1][2], a1, b23.x); fma2(acc2[1][3], a1, b23.y);
            fma2(acc2[2][0], a2, b01.x); fma2(acc2[2][1], a2, b01.y);
            fma2(acc2[2][2], a2, b23.x); fma2(acc2[2][3], a2, b23.y);
            fma2(acc2[3][0], a3, b01.x); fma2(acc2[3][1], a3, b01.y);
            fma2(acc2[3][2], a3, b23.x); fma2(acc2[3][3], a3, b23.y);
        }
        __syncthreads();
    }

    // epilogue: t6 = p6w * (acc/64)
    const float s1 = 1.0f / 64.0f;
    #pragma unroll
    for (int j = 0; j < 4; j++) {
        int m = m0 + (tm << 2) + j;
        int d = tn << 3;
        float f[8];
        unpack2(acc2[j][0], f[0], f[1]);
        unpack2(acc2[j][1], f[2], f[3]);
        unpack2(acc2[j][2], f[4], f[5]);
        unpack2(acc2[j][3], f[6], f[7]);
        const float* pw = &p6w[m * CC + d];
        float4 p0 = *(const float4*)&pw[0];
        float4 p1 = *(const float4*)&pw[4];
        float4 o0, o1;
        o0.x = p0.x * (f[0] * s1); o0.y = p0.y * (f[1] * s1);
        o0.z = p0.z * (f[2] * s1); o0.w = p0.w * (f[3] * s1);
        o1.x = p1.x * (f[4] * s1); o1.y = p1.y * (f[5] * s1);
        o1.z = p1.z * (f[6] * s1); o1.w = p1.w * (f[7] * s1);
        float* dst = &g_t6[((size_t)n * MM + m) * CC + d];
        *(float4*)&dst[0] = o0;
        *(float4*)&dst[4] = o1;
    }
}

// ---------------------------------------------------------------------------
// Kernel 2:  out[n,d,hw] = (1/sqrt(2688)) * sum_m (p5w[m,hw]+1)*A[n,m,hw] * t6[n,m,d]
// GEMM per n: M=4096 (hw, tile 32), N=128 (full), K=2688 (BK 32)
// ---------------------------------------------------------------------------
__global__ __launch_bounds__(128) void k2_proj(const float* __restrict__ x,
                                               const float* __restrict__ p5w,
                                               float* __restrict__ out)
{
    const int n   = blockIdx.y;
    const int hw0 = blockIdx.x * 32;
    const int h   = hw0 >> 6;
    const int w0  = hw0 & 63;
    const int t   = threadIdx.x;
    const int tm  = t >> 4;            // hw rows tm*4..+3
    const int tn  = t & 15;            // d cols tn*8..+7

    __shared__ float Ts[32][AS_STRIDE];    // [kk(m)][hwi]
    __shared__ float T6s[32][BS_STRIDE];   // [kk][d]

    unsigned long long acc2[4][4] = {};
    const float* xn  = x + (size_t)n * CC * HW;
    const float* t6n = g_t6 + (size_t)n * MM * CC;

    const int lkk = t & 31;
    const int lg  = t >> 5;

    #pragma unroll 1
    for (int mc = 0; mc < MM / 32; mc++) {
        const int mb = mc * 32;

        // gather T7 tile: (p5+1) * shifted x, 8 elems/thread, coalesced over hwi
        #pragma unroll
        for (int i = 0; i < 8; i++) {
            int hwi = lkk;
            int kk  = i * 4 + lg;
            int m   = mb + kk;
            int c   = m / RKT;
            int rk  = m - c * RKT;
            int hh  = h + 3 * (rk / 3) - 9;
            int ww  = w0 + hwi + 2 * (rk % 3) - 2;
            float v = 0.0f;
            if ((unsigned)hh < 64u && (unsigned)ww < 64u)
                v = xn[c * HW + (hh << 6) + ww];
            float p = p5w[(size_t)m * HW + hw0 + hwi];
            Ts[kk][hwi] = (p + 1.0f) * v;
        }
        // load t6 tile: 32k x 128d, float4 per thread x8, coalesced over d
        #pragma unroll
        for (int i = 0; i < 8; i++) {
            int idx = i * 128 + t;           // 0..1023 float4 slots
            int kk  = idx >> 5;              // 0..31
            int dq  = idx & 31;              // d = dq*4
            float4 v = *(const float4*)&t6n[(mb + kk) * CC + (dq << 2)];
            *(float4*)&T6s[kk][dq << 2] = v;
        }
        __syncthreads();

        #pragma unroll 16
        for (int kk = 0; kk < 32; kk++) {
            float4 a4 = *(const float4*)&Ts[kk][tm << 2];
            ulonglong2 b01 = *(const ulonglong2*)&T6s[kk][tn << 3];
            ulonglong2 b23 = *(const ulonglong2*)&T6s[kk][(tn << 3) + 4];
            unsigned long long a0 = pack_dup(a4.x);
            unsigned long long a1 = pack_dup(a4.y);
            unsigned long long a2 = pack_dup(a4.z);
            unsigned long long a3 = pack_dup(a4.w);
            fma2(acc2[0][0], a0, b01.x); fma2(acc2[0][1], a0, b01.y);
            fma2(acc2[0][2], a0, b23.x); fma2(acc2[0][3], a0, b23.y);
            fma2(acc2[1][0], a1, b01.x); fma2(acc2[1][1], a1, b01.y);
            fma2(acc2[1][2], a1, b23.x); fma2(acc2[1][3], a1, b23.y);
            fma2(acc2[2][0], a2, b01.x); fma2(acc2[2][1], a2, b01.y);
            fma2(acc2[2][2], a2, b23.x); fma2(acc2[2][3], a2, b23.y);
            fma2(acc2[3][0], a3, b01.x); fma2(acc2[3][1], a3, b01.y);
            fma2(acc2[3][2], a3, b23.x); fma2(acc2[3][3], a3, b23.y);
        }
        __syncthreads();
    }

    // epilogue: out[(n*C + d)*HW + hw], float4 along hw
    const float s2 = 1.0f / sqrtf((float)MM);
    float accf[4][8];
    #pragma unroll
    for (int j = 0; j < 4; j++) {
        unpack2(acc2[j][0], accf[j][0], accf[j][1]);
        unpack2(acc2[j][1], accf[j][2], accf[j][3]);
        unpack2(acc2[j][2], accf[j][4], accf[j][5]);
        unpack2(acc2[j][3], accf[j][6], accf[j][7]);
    }
    const int hwb = hw0 + (tm << 2);
    #pragma unroll
    for (int jj = 0; jj < 8; jj++) {
        int d = (tn << 3) + jj;
        float4 o;
        o.x = accf[0][jj] * s2;
        o.y = accf[1][jj] * s2;
        o.z = accf[2][jj] * s2;
        o.w = accf[3][jj] * s2;
        *(float4*)&out[((size_t)n * CC + d) * HW + hwb] = o;
    }
}

extern "C" void kernel_launch(void* const* d_in, const int* in_sizes, int n_in,
                              void* d_out, int out_size)
{
    const float* x   = (const float*)d_in[0];   // (4,128,64,64)
    const float* p5w = (const float*)d_in[1];   // (1,128,7,3,64,64)
    const float* p6w = (const float*)d_in[2];   // (1,128,7,3,128)
    float* out = (float*)d_out;                 // (4,128,64,64)

    k1_corr<<<dim3(MM / 32, NB), 128>>>(x, p6w);
    k2_proj<<<dim3(HW / 32, NB), 128>>>(x, p5w, out);
}

// round 10
// speedup vs baseline: 1.5154x; 1.1028x over previous
#include <cuda_runtime.h>

// Problem constants
#define NB 4
#define CC 128
#define HW 4096       // 64*64
#define RKT 21        // 7*3 taps
#define MM (CC*RKT)   // 2688

// scratch: t6[n, m, d]  (4 * 2688 * 128 floats = 5.5 MB)
__device__ float g_t6[NB * MM * CC];

// ---- packed f32x2 helpers (sm_103a FFMA2 path) -----------------------------
__device__ __forceinline__ unsigned long long pack_dup(float a) {
    unsigned long long r;
    asm("mov.b64 %0, {%1, %1};" : "=l"(r) : "f"(a));
    return r;
}
__device__ __forceinline__ void fma2(unsigned long long& acc,
                                     unsigned long long a,
                                     unsigned long long b) {
    asm("fma.rn.f32x2 %0, %1, %2, %0;" : "+l"(acc) : "l"(a), "l"(b));
}
__device__ __forceinline__ void unpack2(unsigned long long v, float& lo, float& hi) {
    asm("mov.b64 {%0, %1}, %2;" : "=f"(lo), "=f"(hi) : "l"(v));
}

// Tile geometry (both kernels): block = 128 threads, tile = 32(M) x 128(d), BK=32
// micro-tile per thread: 4 M-rows x 8 d-cols (4 f32x2 pairs) = 16 FFMA2 / kk
#define AS_STRIDE 36    // 32 + 4 pad
#define BS_STRIDE 132   // 128 + 4 pad

// ---------------------------------------------------------------------------
// Kernel 1:  t6[n,m,d] = p6w[m,d] * (1/64) * sum_hw A[n,m,hw] * x[n,d,hw]
//   A[n,m,hw] = x[n, c, h+dr, w+dk]  (zero outside), m = c*21 + rk
// GEMM per n: M=2688 (tile 32), N=128 (full), K=4096 (BK 32)
// Software-pipelined: prefetch next K-chunk's LDG into regs during compute.
// ---------------------------------------------------------------------------
__global__ __launch_bounds__(128) void k1_corr(const float* __restrict__ x,
                                               const float* __restrict__ p6w)
{
    const int n  = blockIdx.y;
    const int m0 = blockIdx.x * 32;
    const int t  = threadIdx.x;
    const int tm = t >> 4;    // 0..7  -> m rows tm*4..+3
    const int tn = t & 15;    // 0..15 -> d cols tn*8..+7

    __shared__ float As[32][AS_STRIDE];   // [kk][mi]
    __shared__ float Bs[32][BS_STRIDE];   // [kk][d]
    __shared__ int s_c[32], s_dr[32], s_dk[32];

    if (t < 32) {
        int m  = m0 + t;
        int c  = m / RKT;
        int rk = m - c * RKT;
        s_c[t]  = c;
        s_dr[t] = 3 * (rk / 3) - 9;
        s_dk[t] = 2 * (rk % 3) - 2;
    }
    __syncthreads();

    unsigned long long acc2[4][4] = {};   // [m-row j][d-pair p]
    const float* xn = x + (size_t)n * CC * HW;

    const int lkk = t & 31;   // lane's kk for gathers
    const int lg  = t >> 5;   // 0..3

    float aPre[8];
    float bPre[32];

    // ---- prologue: load kc = 0 ----
    {
        const int h  = 0;
        const int w0 = 0;
        #pragma unroll
        for (int i = 0; i < 8; i++) {
            int mi = i * 4 + lg;
            int hh = h + s_dr[mi];
            int ww = w0 + lkk + s_dk[mi];
            float v = 0.0f;
            if ((unsigned)hh < 64u && (unsigned)ww < 64u)
                v = xn[s_c[mi] * HW + (hh << 6) + ww];
            aPre[i] = v;
        }
        int hw = lkk;
        #pragma unroll
        for (int j = 0; j < 32; j++)
            bPre[j] = xn[(lg + (j << 2)) * HW + hw];
    }

    #pragma unroll 1
    for (int kc = 0; kc < HW / 32; kc++) {
        // ---- stage: STS prefetched tile ----
        #pragma unroll
        for (int i = 0; i < 8; i++)
            As[lkk][i * 4 + lg] = aPre[i];
        #pragma unroll
        for (int j = 0; j < 32; j++)
            Bs[lkk][lg + (j << 2)] = bPre[j];
        __syncthreads();

        // ---- prefetch kc+1 (overlaps compute) ----
        if (kc + 1 < HW / 32) {
            const int h  = (kc + 1) >> 1;
            const int w0 = ((kc + 1) & 1) << 5;
            #pragma unroll
            for (int i = 0; i < 8; i++) {
                int mi = i * 4 + lg;
                int hh = h + s_dr[mi];
                int ww = w0 + lkk + s_dk[mi];
                float v = 0.0f;
                if ((unsigned)hh < 64u && (unsigned)ww < 64u)
                    v = xn[s_c[mi] * HW + (hh << 6) + ww];
                aPre[i] = v;
            }
            int hw = ((kc + 1) << 5) + lkk;
            #pragma unroll
            for (int j = 0; j < 32; j++)
                bPre[j] = xn[(lg + (j << 2)) * HW + hw];
        }

        // ---- compute 32 kk ----
        #pragma unroll 16
        for (int kk = 0; kk < 32; kk++) {
            float4 a4 = *(const float4*)&As[kk][tm << 2];
            ulonglong2 b01 = *(const ulonglong2*)&Bs[kk][tn << 3];
            ulonglong2 b23 = *(const ulonglong2*)&Bs[kk][(tn << 3) + 4];
            unsigned long long a0 = pack_dup(a4.x);
            unsigned long long a1 = pack_dup(a4.y);
            unsigned long long a2 = pack_dup(a4.z);
            unsigned long long a3 = pack_dup(a4.w);
            fma2(acc2[0][0], a0, b01.x); fma2(acc2[0][1], a0, b01.y);
            fma2(acc2[0][2], a0, b23.x); fma2(acc2[0][3], a0, b23.y);
            fma2(acc2[1][0], a1, b01.x); fma2(acc2[1][1], a1, b01.y);
            fma2(acc2[1][2], a1, b23.x); fma2(acc2[1][3], a1, b23.y);
            fma2(acc2[2][0], a2, b01.x); fma2(acc2[2][1], a2, b01.y);
            fma2(acc2[2][2], a2, b23.x); fma2(acc2[2][3], a2, b23.y);
            fma2(acc2[3][0], a3, b01.x); fma2(acc2[3][1], a3, b01.y);
            fma2(acc2[3][2], a3, b23.x); fma2(acc2[3][3], a3, b23.y);
        }
        __syncthreads();
    }

    // epilogue: t6 = p6w * (acc/64)
    const float s1 = 1.0f / 64.0f;
    #pragma unroll
    for (int j = 0; j < 4; j++) {
        int m = m0 + (tm << 2) + j;
        int d = tn << 3;
        float f[8];
        unpack2(acc2[j][0], f[0], f[1]);
        unpack2(acc2[j][1], f[2], f[3]);
        unpack2(acc2[j][2], f[4], f[5]);
        unpack2(acc2[j][3], f[6], f[7]);
        const float* pw = &p6w[m * CC + d];
        float4 p0 = *(const float4*)&pw[0];
        float4 p1 = *(const float4*)&pw[4];
        float4 o0, o1;
        o0.x = p0.x * (f[0] * s1); o0.y = p0.y * (f[1] * s1);
        o0.z = p0.z * (f[2] * s1); o0.w = p0.w * (f[3] * s1);
        o1.x = p1.x * (f[4] * s1); o1.y = p1.y * (f[5] * s1);
        o1.z = p1.z * (f[6] * s1); o1.w = p1.w * (f[7] * s1);
        float* dst = &g_t6[((size_t)n * MM + m) * CC + d];
        *(float4*)&dst[0] = o0;
        *(float4*)&dst[4] = o1;
    }
}

// ---------------------------------------------------------------------------
// Kernel 2:  out[n,d,hw] = (1/sqrt(2688)) * sum_m (p5w[m,hw]+1)*A[n,m,hw] * t6[n,m,d]
// GEMM per n: M=4096 (hw, tile 32), N=128 (full), K=2688 (BK 32)
// Software-pipelined like k1.
// ---------------------------------------------------------------------------
__global__ __launch_bounds__(128) void k2_proj(const float* __restrict__ x,
                                               const float* __restrict__ p5w,
                                               float* __restrict__ out)
{
    const int n   = blockIdx.y;
    const int hw0 = blockIdx.x * 32;
    const int h   = hw0 >> 6;
    const int w0  = hw0 & 63;
    const int t   = threadIdx.x;
    const int tm  = t >> 4;            // hw rows tm*4..+3
    const int tn  = t & 15;            // d cols tn*8..+7

    __shared__ float Ts[32][AS_STRIDE];    // [kk(m)][hwi]
    __shared__ float T6s[32][BS_STRIDE];   // [kk][d]

    unsigned long long acc2[4][4] = {};
    const float* xn  = x + (size_t)n * CC * HW;
    const float* t6n = g_t6 + (size_t)n * MM * CC;

    const int lkk = t & 31;
    const int lg  = t >> 5;

    float  vPre[8];
    float  pPre[8];
    float4 tPre[8];

    // ---- prologue: load mc = 0 ----
    {
        const int mb = 0;
        #pragma unroll
        for (int i = 0; i < 8; i++) {
            int kk  = i * 4 + lg;
            int m   = mb + kk;
            int c   = m / RKT;
            int rk  = m - c * RKT;
            int hh  = h + 3 * (rk / 3) - 9;
            int ww  = w0 + lkk + 2 * (rk % 3) - 2;
            float v = 0.0f;
            if ((unsigned)hh < 64u && (unsigned)ww < 64u)
                v = xn[c * HW + (hh << 6) + ww];
            vPre[i] = v;
            pPre[i] = p5w[(size_t)m * HW + hw0 + lkk];
        }
        #pragma unroll
        for (int i = 0; i < 8; i++) {
            int idx = i * 128 + t;
            int kk  = idx >> 5;
            int dq  = idx & 31;
            tPre[i] = *(const float4*)&t6n[(mb + kk) * CC + (dq << 2)];
        }
    }

    #pragma unroll 1
    for (int mc = 0; mc < MM / 32; mc++) {
        // ---- stage: STS prefetched tile ----
        #pragma unroll
        for (int i = 0; i < 8; i++) {
            int kk = i * 4 + lg;
            Ts[kk][lkk] = (pPre[i] + 1.0f) * vPre[i];
        }
        #pragma unroll
        for (int i = 0; i < 8; i++) {
            int idx = i * 128 + t;
            int kk  = idx >> 5;
            int dq  = idx & 31;
            *(float4*)&T6s[kk][dq << 2] = tPre[i];
        }
        __syncthreads();

        // ---- prefetch mc+1 (overlaps compute) ----
        if (mc + 1 < MM / 32) {
            const int mb = (mc + 1) * 32;
            #pragma unroll
            for (int i = 0; i < 8; i++) {
                int kk  = i * 4 + lg;
                int m   = mb + kk;
                int c   = m / RKT;
                int rk  = m - c * RKT;
                int hh  = h + 3 * (rk / 3) - 9;
                int ww  = w0 + lkk + 2 * (rk % 3) - 2;
                float v = 0.0f;
                if ((unsigned)hh < 64u && (unsigned)ww < 64u)
                    v = xn[c * HW + (hh << 6) + ww];
                vPre[i] = v;
                pPre[i] = p5w[(size_t)m * HW + hw0 + lkk];
            }
            #pragma unroll
            for (int i = 0; i < 8; i++) {
                int idx = i * 128 + t;
                int kk  = idx >> 5;
                int dq  = idx & 31;
                tPre[i] = *(const float4*)&t6n[(mb + kk) * CC + (dq << 2)];
            }
        }

        // ---- compute 32 kk ----
        #pragma unroll 16
        for (int kk = 0; kk < 32; kk++) {
            float4 a4 = *(const float4*)&Ts[kk][tm << 2];
            ulonglong2 b01 = *(const ulonglong2*)&T6s[kk][tn << 3];
            ulonglong2 b23 = *(const ulonglong2*)&T6s[kk][(tn << 3) + 4];
            unsigned long long a0 = pack_dup(a4.x);
            unsigned long long a1 = pack_dup(a4.y);
            unsigned long long a2 = pack_dup(a4.z);
            unsigned long long a3 = pack_dup(a4.w);
            fma2(acc2[0][0], a0, b01.x); fma2(acc2[0][1], a0, b01.y);
            fma2(acc2[0][2], a0, b23.x); fma2(acc2[0][3], a0, b23.y);
            fma2(acc2[1][0], a1, b01.x); fma2(acc2[1][1], a1, b01.y);
            fma2(acc2[1][2], a1, b23.x); fma2(acc2[1][3], a1, b23.y);
            fma2(acc2[2][0], a2, b01.x); fma2(acc2[2][1], a2, b01.y);
            fma2(acc2[2][2], a2, b23.x); fma2(acc2[2][3], a2, b23.y);
            fma2(acc2[3][0], a3, b01.x); fma2(acc2[3][1], a3, b01.y);
            fma2(acc2[3][2], a3, b23.x); fma2(acc2[3][3], a3, b23.y);
        }
        __syncthreads();
    }

    // epilogue: out[(n*C + d)*HW + hw], float4 along hw
    const float s2 = 1.0f / sqrtf((float)MM);
    float accf[4][8];
    #pragma unroll
    for (int j = 0; j < 4; j++) {
        unpack2(acc2[j][0], accf[j][0], accf[j][1]);
        unpack2(acc2[j][1], accf[j][2], accf[j][3]);
        unpack2(acc2[j][2], accf[j][4], accf[j][5]);
        unpack2(acc2[j][3], accf[j][6], accf[j][7]);
    }
    const int hwb = hw0 + (tm << 2);
    #pragma unroll
    for (int jj = 0; jj < 8; jj++) {
        int d = (tn << 3) + jj;
        float4 o;
        o.x = accf[0][jj] * s2;
        o.y = accf[1][jj] * s2;
        o.z = accf[2][jj] * s2;
        o.w = accf[3][jj] * s2;
        *(float4*)&out[((size_t)n * CC + d) * HW + hwb] = o;
    }
}

extern "C" void kernel_launch(void* const* d_in, const int* in_sizes, int n_in,
                              void* d_out, int out_size)
{
    const float* x   = (const float*)d_in[0];   // (4,128,64,64)
    const float* p5w = (const float*)d_in[1];   // (1,128,7,3,64,64)
    const float* p6w = (const float*)d_in[2];   // (1,128,7,3,128)
    float* out = (float*)d_out;                 // (4,128,64,64)

    k1_corr<<<dim3(MM / 32, NB), 128>>>(x, p6w);
    k2_proj<<<dim3(HW / 32, NB), 128>>>(x, p5w, out);
}

// round 14
// speedup vs baseline: 3.3752x; 2.2272x over previous
#include <cuda_runtime.h>
#include <cuda_bf16.h>
#include <cstdint>

// Problem constants
#define NBATCH 4
#define CCH 128
#define HWD 4096      // 64*64
#define RKT 21
#define MMK 2688      // 128*21
#define STR 40        // bf16 row stride (80B): conflict-free ldmatrix

// t6 stored TRANSPOSED [n][d][m], bf16 hi + lo (2.75 MB each)
__device__ __nv_bfloat16 g_t6hi[(size_t)NBATCH * CCH * MMK];
__device__ __nv_bfloat16 g_t6lo[(size_t)NBATCH * CCH * MMK];

// ---------------- helpers ----------------
static __device__ __forceinline__ uint32_t cvta_sm(const void* p) {
    uint32_t a;
    asm("{ .reg .u64 t; cvta.to.shared.u64 t, %1; cvt.u32.u64 %0, t; }" : "=r"(a) : "l"(p));
    return a;
}
static __device__ __forceinline__ void ldsm4(uint32_t* r, uint32_t a) {
    asm volatile("ldmatrix.sync.aligned.m8n8.x4.shared.b16 {%0,%1,%2,%3}, [%4];"
        : "=r"(r[0]), "=r"(r[1]), "=r"(r[2]), "=r"(r[3]) : "r"(a));
}
static __device__ __forceinline__ void ldsm4t(uint32_t* r, uint32_t a) {
    asm volatile("ldmatrix.sync.aligned.m8n8.x4.trans.shared.b16 {%0,%1,%2,%3}, [%4];"
        : "=r"(r[0]), "=r"(r[1]), "=r"(r[2]), "=r"(r[3]) : "r"(a));
}
static __device__ __forceinline__ void ldsm2(uint32_t* r, uint32_t a) {
    asm volatile("ldmatrix.sync.aligned.m8n8.x2.shared.b16 {%0,%1}, [%2];"
        : "=r"(r[0]), "=r"(r[1]) : "r"(a));
}
static __device__ __forceinline__ void mma_bf16(float* c, const uint32_t* a, const uint32_t* b) {
    asm volatile(
        "mma.sync.aligned.m16n8k16.row.col.f32.bf16.bf16.f32 "
        "{%0,%1,%2,%3}, {%4,%5,%6,%7}, {%8,%9}, {%0,%1,%2,%3};"
        : "+f"(c[0]), "+f"(c[1]), "+f"(c[2]), "+f"(c[3])
        : "r"(a[0]), "r"(a[1]), "r"(a[2]), "r"(a[3]), "r"(b[0]), "r"(b[1]));
}
// split float2 into packed bf16x2 hi and lo (compensation) words
static __device__ __forceinline__ void split2(float vx, float vy, uint32_t& hi, uint32_t& lo) {
    __nv_bfloat16 hx = __float2bfloat16(vx), hy = __float2bfloat16(vy);
    __nv_bfloat16 lx = __float2bfloat16(vx - __bfloat162float(hx));
    __nv_bfloat16 ly = __float2bfloat16(vy - __bfloat162float(hy));
    hi = (uint32_t)__bfloat16_as_ushort(hx) | ((uint32_t)__bfloat16_as_ushort(hy) << 16);
    lo = (uint32_t)__bfloat16_as_ushort(lx) | ((uint32_t)__bfloat16_as_ushort(ly) << 16);
}

// ---------------------------------------------------------------------------
// Kernel 1: t3T[d][m] = (1/64) sum_hw x[d,hw] * A[m,hw];  t6T = p6w*t3 (split)
// CTA: M = d (128, all), N = m-tile 32, K = hw 4096 (BK=32).
// Warp w: d-slice [32w, 32w+32). Both operands K-contiguous rows.
// ---------------------------------------------------------------------------
__global__ __launch_bounds__(128) void k1_corr(const float* __restrict__ x,
                                               const float* __restrict__ p6w)
{
    __shared__ __nv_bfloat16 Xhi[128 * STR], Xlo[128 * STR];
    __shared__ __nv_bfloat16 Thi[32 * STR],  Tlo[32 * STR];

    const int n = blockIdx.y, m0 = blockIdx.x * 32;
    const int t = threadIdx.x, warp = t >> 5, lane = t & 31;
    const float* xn = x + (size_t)n * CCH * HWD;

    float acc[2][4][4] = {};
    const int jr = t & 15, r0 = t >> 4;   // staging: 16 lanes per row

    for (int kb = 0; kb < 128; kb++) {
        const int h = kb >> 1, w0 = (kb & 1) << 5;
        // stage X[d][k] : 128 rows x 32 k, coalesced float2, conflict-free STS
        #pragma unroll
        for (int p = 0; p < 16; p++) {
            int d = r0 + (p << 3);
            const float2 v = *(const float2*)&xn[d * HWD + h * 64 + w0 + (jr << 1)];
            uint32_t hi, lo; split2(v.x, v.y, hi, lo);
            *(uint32_t*)&Xhi[d * STR + (jr << 1)] = hi;
            *(uint32_t*)&Xlo[d * STR + (jr << 1)] = lo;
        }
        // stage T[m][k] : gathered taps, 32 rows x 32 k
        #pragma unroll
        for (int p = 0; p < 4; p++) {
            int mr = r0 + (p << 3);
            int m = m0 + mr, c = m / RKT, rk = m - c * RKT;
            int dr = 3 * (rk / 3) - 9, dk = 2 * (rk % 3) - 2;
            int hh = h + dr, ww = w0 + (jr << 1) + dk;   // ww even
            float2 v = make_float2(0.f, 0.f);
            if ((unsigned)hh < 64u && (unsigned)ww < 64u)
                v = *(const float2*)&xn[c * HWD + hh * 64 + ww];
            uint32_t hi, lo; split2(v.x, v.y, hi, lo);
            *(uint32_t*)&Thi[mr * STR + (jr << 1)] = hi;
            *(uint32_t*)&Tlo[mr * STR + (jr << 1)] = lo;
        }
        __syncthreads();

        #pragma unroll
        for (int ks = 0; ks < 2; ks++) {
            uint32_t ah[2][4], al[2][4], bh[4][2], bl[4][2];
            #pragma unroll
            for (int tt = 0; tt < 2; tt++) {
                int row = (warp << 5) + (tt << 4) + (lane & 15);
                int col = (ks << 4) + ((lane >> 4) << 3);
                uint32_t off = (uint32_t)(row * STR + col) * 2;
                ldsm4(ah[tt], cvta_sm(Xhi) + off);
                ldsm4(al[tt], cvta_sm(Xlo) + off);
            }
            #pragma unroll
            for (int j = 0; j < 4; j++) {
                int row = (j << 3) + (lane & 7);
                int col = (ks << 4) + (((lane >> 3) & 1) << 3);
                uint32_t off = (uint32_t)(row * STR + col) * 2;
                ldsm2(bh[j], cvta_sm(Thi) + off);
                ldsm2(bl[j], cvta_sm(Tlo) + off);
            }
            #pragma unroll
            for (int tt = 0; tt < 2; tt++)
                #pragma unroll
                for (int j = 0; j < 4; j++) {
                    mma_bf16(acc[tt][j], ah[tt], bh[j]);
                    mma_bf16(acc[tt][j], ah[tt], bl[j]);
                    mma_bf16(acc[tt][j], al[tt], bh[j]);
                }
        }
        __syncthreads();
    }

    // epilogue: t6T[d][m] = p6w[m,d] * acc/64, split hi/lo, bf16x2 stores
    const float s1 = 1.0f / 64.0f;
    #pragma unroll
    for (int tt = 0; tt < 2; tt++)
        #pragma unroll
        for (int j = 0; j < 4; j++) {
            int d0 = (warp << 5) + (tt << 4) + (lane >> 2);
            int m  = m0 + (j << 3) + ((lane & 3) << 1);
            #pragma unroll
            for (int half = 0; half < 2; half++) {
                int d = d0 + half * 8;
                float v0 = acc[tt][j][half * 2 + 0] * s1 * p6w[m * CCH + d];
                float v1 = acc[tt][j][half * 2 + 1] * s1 * p6w[(m + 1) * CCH + d];
                uint32_t hi, lo; split2(v0, v1, hi, lo);
                size_t o = ((size_t)(n * CCH + d)) * MMK + m;
                *(uint32_t*)&g_t6hi[o] = hi;
                *(uint32_t*)&g_t6lo[o] = lo;
            }
        }
}

// ---------------------------------------------------------------------------
// Kernel 2: out[hw][d] = (1/sqrt(2688)) sum_m t7[m,hw] * t6[m,d]
// CTA: M = hw-tile 32, N = d (128, all), K = m 2688 (BK=32).
// A = t7 staged [k=m][hw] (hw-contiguous writes), loaded via ldmatrix.trans.
// B = t6T[d][m] rows copied straight from g_t6 (m-contiguous).
// ---------------------------------------------------------------------------
__global__ __launch_bounds__(128) void k2_proj(const float* __restrict__ x,
                                               const float* __restrict__ p5w,
                                               float* __restrict__ out)
{
    __shared__ __nv_bfloat16 T7hi[32 * STR],  T7lo[32 * STR];
    __shared__ __nv_bfloat16 T6hi[128 * STR], T6lo[128 * STR];

    const int n = blockIdx.y, hw0 = blockIdx.x * 32;
    const int t = threadIdx.x, warp = t >> 5, lane = t & 31;
    const float* xn = x + (size_t)n * CCH * HWD;
    const __nv_bfloat16* t6h = g_t6hi + (size_t)n * CCH * MMK;
    const __nv_bfloat16* t6l = g_t6lo + (size_t)n * CCH * MMK;

    float acc[2][4][4] = {};
    const int jr = t & 15, r0 = t >> 4;

    for (int kb = 0; kb < MMK / 32; kb++) {
        const int mb = kb << 5;
        // stage T7[k=m][hw]: 32 rows x 32 hw, hw-contiguous (coalesced p5w/x)
        #pragma unroll
        for (int p = 0; p < 4; p++) {
            int mr = r0 + (p << 3);
            int m = mb + mr, c = m / RKT, rk = m - c * RKT;
            int dr = 3 * (rk / 3) - 9, dk = 2 * (rk % 3) - 2;
            int hwg = hw0 + (jr << 1);
            int h = hwg >> 6, w = hwg & 63;
            int hh = h + dr, ww = w + dk;     // ww even
            float2 xv = make_float2(0.f, 0.f);
            if ((unsigned)hh < 64u && (unsigned)ww < 64u)
                xv = *(const float2*)&xn[c * HWD + hh * 64 + ww];
            const float2 pv = *(const float2*)&p5w[(size_t)m * HWD + hwg];
            uint32_t hi, lo;
            split2((pv.x + 1.0f) * xv.x, (pv.y + 1.0f) * xv.y, hi, lo);
            *(uint32_t*)&T7hi[mr * STR + (jr << 1)] = hi;
            *(uint32_t*)&T7lo[mr * STR + (jr << 1)] = lo;
        }
        // stage T6[d][k]: 128 rows x 32 k bf16 = 64B/row, uint4 copies
        #pragma unroll
        for (int p = 0; p < 4; p++) {
            int slot = t + (p << 7);
            int d = slot >> 2, ch = slot & 3;
            *(uint4*)((char*)&T6hi[d * STR] + (ch << 4)) =
                *(const uint4*)((const char*)(t6h + (size_t)d * MMK + mb) + (ch << 4));
            *(uint4*)((char*)&T6lo[d * STR] + (ch << 4)) =
                *(const uint4*)((const char*)(t6l + (size_t)d * MMK + mb) + (ch << 4));
        }
        __syncthreads();

        #pragma unroll
        for (int ks = 0; ks < 2; ks++) {
            uint32_t ah[2][4], al[2][4], bh[4][2], bl[4][2];
            #pragma unroll
            for (int tt = 0; tt < 2; tt++) {   // A via trans: stored [k][hw]
                int row = (ks << 4) + ((lane >> 4) << 3) + (lane & 7);
                int col = (tt << 4) + (((lane >> 3) & 1) << 3);
                uint32_t off = (uint32_t)(row * STR + col) * 2;
                ldsm4t(ah[tt], cvta_sm(T7hi) + off);
                ldsm4t(al[tt], cvta_sm(T7lo) + off);
            }
            #pragma unroll
            for (int j = 0; j < 4; j++) {      // B: t6T rows d
                int row = (warp << 5) + (j << 3) + (lane & 7);
                int col = (ks << 4) + (((lane >> 3) & 1) << 3);
                uint32_t off = (uint32_t)(row * STR + col) * 2;
                ldsm2(bh[j], cvta_sm(T6hi) + off);
                ldsm2(bl[j], cvta_sm(T6lo) + off);
            }
            #pragma unroll
            for (int tt = 0; tt < 2; tt++)
                #pragma unroll
                for (int j = 0; j < 4; j++) {
                    mma_bf16(acc[tt][j], ah[tt], bh[j]);
                    mma_bf16(acc[tt][j], ah[tt], bl[j]);
                    mma_bf16(acc[tt][j], al[tt], bh[j]);
                }
        }
        __syncthreads();
    }

    // epilogue: out[(n*C + d)*HW + hw]
    const float s2 = 1.0f / sqrtf((float)MMK);
    #pragma unroll
    for (int tt = 0; tt < 2; tt++)
        #pragma unroll
        for (int j = 0; j < 4; j++) {
            int hwb = hw0 + (tt << 4) + (lane >> 2);
            int d   = (warp << 5) + (j << 3) + ((lane & 3) << 1);
            #pragma unroll
            for (int half = 0; half < 2; half++) {
                int hw = hwb + half * 8;
                out[((size_t)(n * CCH + d))     * HWD + hw] = acc[tt][j][half * 2 + 0] * s2;
                out[((size_t)(n * CCH + d + 1)) * HWD + hw] = acc[tt][j][half * 2 + 1] * s2;
            }
        }
}

extern "C" void kernel_launch(void* const* d_in, const int* in_sizes, int n_in,
                              void* d_out, int out_size)
{
    const float* x   = (const float*)d_in[0];   // (4,128,64,64)
    const float* p5w = (const float*)d_in[1];   // (1,128,7,3,64,64)
    const float* p6w = (const float*)d_in[2];   // (1,128,7,3,128)
    float* out = (float*)d_out;                 // (4,128,64,64)

    k1_corr<<<dim3(MMK / 32, NBATCH), 128>>>(x, p6w);
    k2_proj<<<dim3(HWD / 32, NBATCH), 128>>>(x, p5w, out);
}

// round 15
// speedup vs baseline: 3.8944x; 1.1538x over previous
#include <cuda_runtime.h>
#include <cuda_bf16.h>
#include <cstdint>

// Problem constants
#define NBATCH 4
#define CCH 128
#define HWD 4096      // 64*64
#define RKT 21
#define MMK 2688      // 128*21
#define STR 40        // bf16 row stride (80B): conflict-free ldmatrix

// t6 stored TRANSPOSED [n][d][m], bf16 hi + lo (2.75 MB each)
__device__ __nv_bfloat16 g_t6hi[(size_t)NBATCH * CCH * MMK];
__device__ __nv_bfloat16 g_t6lo[(size_t)NBATCH * CCH * MMK];

// per-stage smem layout (bytes). Big tiles (128xSTR) first, then small (32xSTR).
#define BIGHI_OFF 0
#define BIGLO_OFF 10240
#define SMLHI_OFF 20480
#define SMLLO_OFF 23040
#define STAGE_BYTES 25600
#define SMEM_TOTAL (2 * STAGE_BYTES)   // 51200

// ---------------- helpers ----------------
static __device__ __forceinline__ uint32_t cvta_sm(const void* p) {
    uint32_t a;
    asm("{ .reg .u64 t; cvta.to.shared.u64 t, %1; cvt.u32.u64 %0, t; }" : "=r"(a) : "l"(p));
    return a;
}
static __device__ __forceinline__ void ldsm4(uint32_t* r, uint32_t a) {
    asm volatile("ldmatrix.sync.aligned.m8n8.x4.shared.b16 {%0,%1,%2,%3}, [%4];"
        : "=r"(r[0]), "=r"(r[1]), "=r"(r[2]), "=r"(r[3]) : "r"(a));
}
static __device__ __forceinline__ void ldsm4t(uint32_t* r, uint32_t a) {
    asm volatile("ldmatrix.sync.aligned.m8n8.x4.trans.shared.b16 {%0,%1,%2,%3}, [%4];"
        : "=r"(r[0]), "=r"(r[1]), "=r"(r[2]), "=r"(r[3]) : "r"(a));
}
static __device__ __forceinline__ void ldsm2(uint32_t* r, uint32_t a) {
    asm volatile("ldmatrix.sync.aligned.m8n8.x2.shared.b16 {%0,%1}, [%2];"
        : "=r"(r[0]), "=r"(r[1]) : "r"(a));
}
static __device__ __forceinline__ void mma_bf16(float* c, const uint32_t* a, const uint32_t* b) {
    asm volatile(
        "mma.sync.aligned.m16n8k16.row.col.f32.bf16.bf16.f32 "
        "{%0,%1,%2,%3}, {%4,%5,%6,%7}, {%8,%9}, {%0,%1,%2,%3};"
        : "+f"(c[0]), "+f"(c[1]), "+f"(c[2]), "+f"(c[3])
        : "r"(a[0]), "r"(a[1]), "r"(a[2]), "r"(a[3]), "r"(b[0]), "r"(b[1]));
}
// split float2 into packed bf16x2 hi and lo (compensation) words
static __device__ __forceinline__ void split2(float vx, float vy, uint32_t& hi, uint32_t& lo) {
    __nv_bfloat16 hx = __float2bfloat16(vx), hy = __float2bfloat16(vy);
    __nv_bfloat16 lx = __float2bfloat16(vx - __bfloat162float(hx));
    __nv_bfloat16 ly = __float2bfloat16(vy - __bfloat162float(hy));
    hi = (uint32_t)__bfloat16_as_ushort(hx) | ((uint32_t)__bfloat16_as_ushort(hy) << 16);
    lo = (uint32_t)__bfloat16_as_ushort(lx) | ((uint32_t)__bfloat16_as_ushort(ly) << 16);
}

// ---------------------------------------------------------------------------
// Kernel 1: t3T[d][m] = (1/64) sum_hw x[d,hw] * A[m,hw];  t6T = p6w*t3 (split)
// CTA: M = d (128, all), N = m-tile 32, K = hw 4096 (BK=32). Double-buffered.
// ---------------------------------------------------------------------------
__global__ __launch_bounds__(128) void k1_corr(const float* __restrict__ x,
                                               const float* __restrict__ p6w)
{
    extern __shared__ char sm[];
    const uint32_t smb = cvta_sm(sm);

    const int n = blockIdx.y, m0 = blockIdx.x * 32;
    const int t = threadIdx.x, warp = t >> 5, lane = t & 31;
    const float* xn = x + (size_t)n * CCH * HWD;

    float acc[2][4][4] = {};
    const int jr = t & 15, r0 = t >> 4;   // staging: 16 lanes per row

    // gather geometry for the 4 T-rows this thread stages (m fixed per thread)
    int tc[4], tdr[4], tdk[4];
    #pragma unroll
    for (int p = 0; p < 4; p++) {
        int m = m0 + r0 + (p << 3), c = m / RKT, rk = m - c * RKT;
        tc[p] = c; tdr[p] = 3 * (rk / 3) - 9; tdk[p] = 2 * (rk % 3) - 2;
    }

    float2 xv[16], tv[4];

    // ---- prefetch kb = 0 ----
    #pragma unroll
    for (int p = 0; p < 16; p++)
        xv[p] = *(const float2*)&xn[(r0 + (p << 3)) * HWD + (jr << 1)];
    #pragma unroll
    for (int p = 0; p < 4; p++) {
        int hh = tdr[p], ww = (jr << 1) + tdk[p];
        tv[p] = make_float2(0.f, 0.f);
        if ((unsigned)hh < 64u && (unsigned)ww < 64u)
            tv[p] = *(const float2*)&xn[tc[p] * HWD + hh * 64 + ww];
    }
    // ---- stage 0 ----
    {
        char* sb = sm;
        #pragma unroll
        for (int p = 0; p < 16; p++) {
            uint32_t hi, lo; split2(xv[p].x, xv[p].y, hi, lo);
            int boff = ((r0 + (p << 3)) * STR + (jr << 1)) * 2;
            *(uint32_t*)(sb + BIGHI_OFF + boff) = hi;
            *(uint32_t*)(sb + BIGLO_OFF + boff) = lo;
        }
        #pragma unroll
        for (int p = 0; p < 4; p++) {
            uint32_t hi, lo; split2(tv[p].x, tv[p].y, hi, lo);
            int boff = ((r0 + (p << 3)) * STR + (jr << 1)) * 2;
            *(uint32_t*)(sb + SMLHI_OFF + boff) = hi;
            *(uint32_t*)(sb + SMLLO_OFF + boff) = lo;
        }
    }
    __syncthreads();

    for (int kb = 0; kb < 128; kb++) {
        const uint32_t sb = smb + (kb & 1) * STAGE_BYTES;

        // ---- prefetch kb+1 (LDGs drain behind the MMAs) ----
        const bool more = (kb + 1) < 128;
        if (more) {
            const int h = (kb + 1) >> 1, w0 = ((kb + 1) & 1) << 5;
            #pragma unroll
            for (int p = 0; p < 16; p++)
                xv[p] = *(const float2*)&xn[(r0 + (p << 3)) * HWD + h * 64 + w0 + (jr << 1)];
            #pragma unroll
            for (int p = 0; p < 4; p++) {
                int hh = h + tdr[p], ww = w0 + (jr << 1) + tdk[p];
                tv[p] = make_float2(0.f, 0.f);
                if ((unsigned)hh < 64u && (unsigned)ww < 64u)
                    tv[p] = *(const float2*)&xn[tc[p] * HWD + hh * 64 + ww];
            }
        }

        // ---- compute from stage kb&1 ----
        #pragma unroll
        for (int ks = 0; ks < 2; ks++) {
            uint32_t ah[2][4], al[2][4], bh[4][2], bl[4][2];
            #pragma unroll
            for (int tt = 0; tt < 2; tt++) {
                int row = (warp << 5) + (tt << 4) + (lane & 15);
                int col = (ks << 4) + ((lane >> 4) << 3);
                uint32_t off = (uint32_t)(row * STR + col) * 2;
                ldsm4(ah[tt], sb + BIGHI_OFF + off);
                ldsm4(al[tt], sb + BIGLO_OFF + off);
            }
            #pragma unroll
            for (int j = 0; j < 4; j++) {
                int row = (j << 3) + (lane & 7);
                int col = (ks << 4) + (((lane >> 3) & 1) << 3);
                uint32_t off = (uint32_t)(row * STR + col) * 2;
                ldsm2(bh[j], sb + SMLHI_OFF + off);
                ldsm2(bl[j], sb + SMLLO_OFF + off);
            }
            #pragma unroll
            for (int tt = 0; tt < 2; tt++)
                #pragma unroll
                for (int j = 0; j < 4; j++) {
                    mma_bf16(acc[tt][j], ah[tt], bh[j]);
                    mma_bf16(acc[tt][j], ah[tt], bl[j]);
                    mma_bf16(acc[tt][j], al[tt], bh[j]);
                }
        }

        // ---- convert + STS into the other stage ----
        if (more) {
            char* so = sm + ((kb + 1) & 1) * STAGE_BYTES;
            #pragma unroll
            for (int p = 0; p < 16; p++) {
                uint32_t hi, lo; split2(xv[p].x, xv[p].y, hi, lo);
                int boff = ((r0 + (p << 3)) * STR + (jr << 1)) * 2;
                *(uint32_t*)(so + BIGHI_OFF + boff) = hi;
                *(uint32_t*)(so + BIGLO_OFF + boff) = lo;
            }
            #pragma unroll
            for (int p = 0; p < 4; p++) {
                uint32_t hi, lo; split2(tv[p].x, tv[p].y, hi, lo);
                int boff = ((r0 + (p << 3)) * STR + (jr << 1)) * 2;
                *(uint32_t*)(so + SMLHI_OFF + boff) = hi;
                *(uint32_t*)(so + SMLLO_OFF + boff) = lo;
            }
        }
        __syncthreads();
    }

    // epilogue: t6T[d][m] = p6w[m,d] * acc/64, split hi/lo, bf16x2 stores
    const float s1 = 1.0f / 64.0f;
    #pragma unroll
    for (int tt = 0; tt < 2; tt++)
        #pragma unroll
        for (int j = 0; j < 4; j++) {
            int d0 = (warp << 5) + (tt << 4) + (lane >> 2);
            int m  = m0 + (j << 3) + ((lane & 3) << 1);
            #pragma unroll
            for (int half = 0; half < 2; half++) {
                int d = d0 + half * 8;
                float v0 = acc[tt][j][half * 2 + 0] * s1 * p6w[m * CCH + d];
                float v1 = acc[tt][j][half * 2 + 1] * s1 * p6w[(m + 1) * CCH + d];
                uint32_t hi, lo; split2(v0, v1, hi, lo);
                size_t o = ((size_t)(n * CCH + d)) * MMK + m;
                *(uint32_t*)&g_t6hi[o] = hi;
                *(uint32_t*)&g_t6lo[o] = lo;
            }
        }
}

// ---------------------------------------------------------------------------
// Kernel 2: out[hw][d] = (1/sqrt(2688)) sum_m t7[m,hw] * t6[m,d]
// CTA: M = hw-tile 32, N = d (128, all), K = m 2688 (BK=32). Double-buffered.
// ---------------------------------------------------------------------------
__global__ __launch_bounds__(128) void k2_proj(const float* __restrict__ x,
                                               const float* __restrict__ p5w,
                                               float* __restrict__ out)
{
    extern __shared__ char sm[];
    const uint32_t smb = cvta_sm(sm);

    const int n = blockIdx.y, hw0 = blockIdx.x * 32;
    const int t = threadIdx.x, warp = t >> 5, lane = t & 31;
    const float* xn = x + (size_t)n * CCH * HWD;
    const __nv_bfloat16* t6h = g_t6hi + (size_t)n * CCH * MMK;
    const __nv_bfloat16* t6l = g_t6lo + (size_t)n * CCH * MMK;

    float acc[2][4][4] = {};
    const int jr = t & 15, r0 = t >> 4;
    const int hwg = hw0 + (jr << 1);
    const int hq = hwg >> 6, wq = hwg & 63;

    float2 xv[4], pv[4];
    uint4  th[4], tl[4];

    // helper indices for the T6 copy
    const int cd = t >> 2, cch = t & 3;    // 128 rows x 4 chunks over 512 slots... (t + p*128)

    // ---- prefetch kb = 0 ----
    #pragma unroll
    for (int p = 0; p < 4; p++) {
        int m = r0 + (p << 3), c = m / RKT, rk = m - c * RKT;
        int hh = hq + 3 * (rk / 3) - 9, ww = wq + 2 * (rk % 3) - 2;
        xv[p] = make_float2(0.f, 0.f);
        if ((unsigned)hh < 64u && (unsigned)ww < 64u)
            xv[p] = *(const float2*)&xn[c * HWD + hh * 64 + ww];
        pv[p] = *(const float2*)&p5w[(size_t)m * HWD + hwg];
    }
    #pragma unroll
    for (int p = 0; p < 4; p++) {
        int slot = t + (p << 7);
        int d = slot >> 2, ch = slot & 3;
        th[p] = *(const uint4*)((const char*)(t6h + (size_t)d * MMK) + (ch << 4));
        tl[p] = *(const uint4*)((const char*)(t6l + (size_t)d * MMK) + (ch << 4));
    }
    // ---- stage 0 ----
    {
        char* so = sm;
        #pragma unroll
        for (int p = 0; p < 4; p++) {
            uint32_t hi, lo;
            split2((pv[p].x + 1.0f) * xv[p].x, (pv[p].y + 1.0f) * xv[p].y, hi, lo);
            int boff = ((r0 + (p << 3)) * STR + (jr << 1)) * 2;
            *(uint32_t*)(so + SMLHI_OFF + boff) = hi;
            *(uint32_t*)(so + SMLLO_OFF + boff) = lo;
        }
        #pragma unroll
        for (int p = 0; p < 4; p++) {
            int slot = t + (p << 7);
            int d = slot >> 2, ch = slot & 3;
            *(uint4*)(so + BIGHI_OFF + d * (STR * 2) + (ch << 4)) = th[p];
            *(uint4*)(so + BIGLO_OFF + d * (STR * 2) + (ch << 4)) = tl[p];
        }
    }
    __syncthreads();

    for (int kb = 0; kb < MMK / 32; kb++) {
        const uint32_t sb = smb + (kb & 1) * STAGE_BYTES;
        const bool more = (kb + 1) < MMK / 32;

        // ---- prefetch kb+1 ----
        if (more) {
            const int mb = (kb + 1) << 5;
            #pragma unroll
            for (int p = 0; p < 4; p++) {
                int m = mb + r0 + (p << 3), c = m / RKT, rk = m - c * RKT;
                int hh = hq + 3 * (rk / 3) - 9, ww = wq + 2 * (rk % 3) - 2;
                xv[p] = make_float2(0.f, 0.f);
                if ((unsigned)hh < 64u && (unsigned)ww < 64u)
                    xv[p] = *(const float2*)&xn[c * HWD + hh * 64 + ww];
                pv[p] = *(const float2*)&p5w[(size_t)m * HWD + hwg];
            }
            #pragma unroll
            for (int p = 0; p < 4; p++) {
                int slot = t + (p << 7);
                int d = slot >> 2, ch = slot & 3;
                th[p] = *(const uint4*)((const char*)(t6h + (size_t)d * MMK + mb) + (ch << 4));
                tl[p] = *(const uint4*)((const char*)(t6l + (size_t)d * MMK + mb) + (ch << 4));
            }
        }

        // ---- compute from stage kb&1 ----
        #pragma unroll
        for (int ks = 0; ks < 2; ks++) {
            uint32_t ah[2][4], al[2][4], bh[4][2], bl[4][2];
            #pragma unroll
            for (int tt = 0; tt < 2; tt++) {   // A via trans: stored [k=m][hw]
                int row = (ks << 4) + ((lane >> 4) << 3) + (lane & 7);
                int col = (tt << 4) + (((lane >> 3) & 1) << 3);
                uint32_t off = (uint32_t)(row * STR + col) * 2;
                ldsm4t(ah[tt], sb + SMLHI_OFF + off);
                ldsm4t(al[tt], sb + SMLLO_OFF + off);
            }
            #pragma unroll
            for (int j = 0; j < 4; j++) {      // B: t6T rows d
                int row = (warp << 5) + (j << 3) + (lane & 7);
                int col = (ks << 4) + (((lane >> 3) & 1) << 3);
                uint32_t off = (uint32_t)(row * STR + col) * 2;
                ldsm2(bh[j], sb + BIGHI_OFF + off);
                ldsm2(bl[j], sb + BIGLO_OFF + off);
            }
            #pragma unroll
            for (int tt = 0; tt < 2; tt++)
                #pragma unroll
                for (int j = 0; j < 4; j++) {
                    mma_bf16(acc[tt][j], ah[tt], bh[j]);
                    mma_bf16(acc[tt][j], ah[tt], bl[j]);
                    mma_bf16(acc[tt][j], al[tt], bh[j]);
                }
        }

        // ---- convert + STS into other stage ----
        if (more) {
            char* so = sm + ((kb + 1) & 1) * STAGE_BYTES;
            #pragma unroll
            for (int p = 0; p < 4; p++) {
                uint32_t hi, lo;
                split2((pv[p].x + 1.0f) * xv[p].x, (pv[p].y + 1.0f) * xv[p].y, hi, lo);
                int boff = ((r0 + (p << 3)) * STR + (jr << 1)) * 2;
                *(uint32_t*)(so + SMLHI_OFF + boff) = hi;
                *(uint32_t*)(so + SMLLO_OFF + boff) = lo;
            }
            #pragma unroll
            for (int p = 0; p < 4; p++) {
                int slot = t + (p << 7);
                int d = slot >> 2, ch = slot & 3;
                *(uint4*)(so + BIGHI_OFF + d * (STR * 2) + (ch << 4)) = th[p];
                *(uint4*)(so + BIGLO_OFF + d * (STR * 2) + (ch << 4)) = tl[p];
            }
        }
        __syncthreads();
    }

    // epilogue: out[(n*C + d)*HW + hw]
    const float s2 = 1.0f / sqrtf((float)MMK);
    #pragma unroll
    for (int tt = 0; tt < 2; tt++)
        #pragma unroll
        for (int j = 0; j < 4; j++) {
            int hwb = hw0 + (tt << 4) + (lane >> 2);
            int d   = (warp << 5) + (j << 3) + ((lane & 3) << 1);
            #pragma unroll
            for (int half = 0; half < 2; half++) {
                int hw = hwb + half * 8;
                out[((size_t)(n * CCH + d))     * HWD + hw] = acc[tt][j][half * 2 + 0] * s2;
                out[((size_t)(n * CCH + d + 1)) * HWD + hw] = acc[tt][j][half * 2 + 1] * s2;
            }
        }
}

extern "C" void kernel_launch(void* const* d_in, const int* in_sizes, int n_in,
                              void* d_out, int out_size)
{
    const float* x   = (const float*)d_in[0];   // (4,128,64,64)
    const float* p5w = (const float*)d_in[1];   // (1,128,7,3,64,64)
    const float* p6w = (const float*)d_in[2];   // (1,128,7,3,128)
    float* out = (float*)d_out;                 // (4,128,64,64)

    cudaFuncSetAttribute(k1_corr, cudaFuncAttributeMaxDynamicSharedMemorySize, SMEM_TOTAL);
    cudaFuncSetAttribute(k2_proj, cudaFuncAttributeMaxDynamicSharedMemorySize, SMEM_TOTAL);

    k1_corr<<<dim3(MMK / 32, NBATCH), 128, SMEM_TOTAL>>>(x, p6w);
    k2_proj<<<dim3(HWD / 32, NBATCH), 128, SMEM_TOTAL>>>(x, p5w, out);
}

// round 16
// speedup vs baseline: 4.4035x; 1.1307x over previous
#include <cuda_runtime.h>
#include <cuda_bf16.h>
#include <cstdint>

// Problem constants
#define NBATCH 4
#define CCH 128
#define HWD 4096      // 64*64
#define RKT 21
#define MMK 2688      // 128*21
#define STR 40        // bf16 row stride (80B) for 32-col tiles
#define STR2 72       // bf16 row stride (144B) for 64-col T7 tile (conflict-free)

// t6 stored TRANSPOSED [n][d][m], bf16 hi + lo
__device__ __nv_bfloat16 g_t6hi[(size_t)NBATCH * CCH * MMK];
__device__ __nv_bfloat16 g_t6lo[(size_t)NBATCH * CCH * MMK];

// ---- k1 per-stage smem layout (bytes): X 128xSTR, T 64xSTR --------------
#define K1_XHI 0
#define K1_XLO 10240
#define K1_THI 20480
#define K1_TLO 25600
#define K1_STAGE 30720
#define K1_SMEM (2 * K1_STAGE)    // 61440

// ---- k2 per-stage smem layout: T6 128xSTR, T7 32xSTR2 -------------------
#define K2_6HI 0
#define K2_6LO 10240
#define K2_7HI 20480
#define K2_7LO 25088
#define K2_STAGE 29696
#define K2_SMEM (2 * K2_STAGE)    // 59392

// ---------------- helpers ----------------
static __device__ __forceinline__ uint32_t cvta_sm(const void* p) {
    uint32_t a;
    asm("{ .reg .u64 t; cvta.to.shared.u64 t, %1; cvt.u32.u64 %0, t; }" : "=r"(a) : "l"(p));
    return a;
}
static __device__ __forceinline__ void ldsm4(uint32_t* r, uint32_t a) {
    asm volatile("ldmatrix.sync.aligned.m8n8.x4.shared.b16 {%0,%1,%2,%3}, [%4];"
        : "=r"(r[0]), "=r"(r[1]), "=r"(r[2]), "=r"(r[3]) : "r"(a));
}
static __device__ __forceinline__ void ldsm4t(uint32_t* r, uint32_t a) {
    asm volatile("ldmatrix.sync.aligned.m8n8.x4.trans.shared.b16 {%0,%1,%2,%3}, [%4];"
        : "=r"(r[0]), "=r"(r[1]), "=r"(r[2]), "=r"(r[3]) : "r"(a));
}
static __device__ __forceinline__ void ldsm2(uint32_t* r, uint32_t a) {
    asm volatile("ldmatrix.sync.aligned.m8n8.x2.shared.b16 {%0,%1}, [%2];"
        : "=r"(r[0]), "=r"(r[1]) : "r"(a));
}
static __device__ __forceinline__ void mma_bf16(float* c, const uint32_t* a, const uint32_t* b) {
    asm volatile(
        "mma.sync.aligned.m16n8k16.row.col.f32.bf16.bf16.f32 "
        "{%0,%1,%2,%3}, {%4,%5,%6,%7}, {%8,%9}, {%0,%1,%2,%3};"
        : "+f"(c[0]), "+f"(c[1]), "+f"(c[2]), "+f"(c[3])
        : "r"(a[0]), "r"(a[1]), "r"(a[2]), "r"(a[3]), "r"(b[0]), "r"(b[1]));
}
static __device__ __forceinline__ void split2(float vx, float vy, uint32_t& hi, uint32_t& lo) {
    __nv_bfloat16 hx = __float2bfloat16(vx), hy = __float2bfloat16(vy);
    __nv_bfloat16 lx = __float2bfloat16(vx - __bfloat162float(hx));
    __nv_bfloat16 ly = __float2bfloat16(vy - __bfloat162float(hy));
    hi = (uint32_t)__bfloat16_as_ushort(hx) | ((uint32_t)__bfloat16_as_ushort(hy) << 16);
    lo = (uint32_t)__bfloat16_as_ushort(lx) | ((uint32_t)__bfloat16_as_ushort(ly) << 16);
}

// ---------------------------------------------------------------------------
// Kernel 1: t3T[d][m] = (1/64) sum_hw x[d,hw]*A[m,hw]; t6T = p6w*t3 (split)
// CTA: 256 thr, d(128) x m(64), K=hw 4096 (BK=32), double-buffered.
// Warps: wr = m-half (0/1), wc = d-quarter (0..3).
// ---------------------------------------------------------------------------
__global__ __launch_bounds__(256, 2) void k1_corr(const float* __restrict__ x,
                                                  const float* __restrict__ p6w)
{
    extern __shared__ char sm[];
    const uint32_t smb = cvta_sm(sm);

    const int n = blockIdx.y, m0 = blockIdx.x * 64;
    const int t = threadIdx.x, warp = t >> 5, lane = t & 31;
    const int wr = warp >> 2, wc = warp & 3;
    const float* xn = x + (size_t)n * CCH * HWD;

    float acc[2][4][4] = {};
    const int jr = t & 15, r0 = t >> 4;   // 16 lanes x 2 floats = 32 k; r0 in 0..15

    // gather geometry for the 4 T-rows this thread stages
    int tc[4], tdr[4], tdk[4];
    #pragma unroll
    for (int p = 0; p < 4; p++) {
        int m = m0 + r0 + (p << 4), c = m / RKT, rk = m - c * RKT;
        tc[p] = c; tdr[p] = 3 * (rk / 3) - 9; tdk[p] = 2 * (rk % 3) - 2;
    }

    float2 xv[8], tv[4];

    // ---- prefetch kb = 0 ----
    #pragma unroll
    for (int p = 0; p < 8; p++)
        xv[p] = *(const float2*)&xn[(r0 + (p << 4)) * HWD + (jr << 1)];
    #pragma unroll
    for (int p = 0; p < 4; p++) {
        int hh = tdr[p], ww = (jr << 1) + tdk[p];
        tv[p] = make_float2(0.f, 0.f);
        if ((unsigned)hh < 64u && (unsigned)ww < 64u)
            tv[p] = *(const float2*)&xn[tc[p] * HWD + hh * 64 + ww];
    }
    // ---- stage 0 ----
    {
        char* so = sm;
        #pragma unroll
        for (int p = 0; p < 8; p++) {
            uint32_t hi, lo; split2(xv[p].x, xv[p].y, hi, lo);
            int boff = ((r0 + (p << 4)) * STR + (jr << 1)) * 2;
            *(uint32_t*)(so + K1_XHI + boff) = hi;
            *(uint32_t*)(so + K1_XLO + boff) = lo;
        }
        #pragma unroll
        for (int p = 0; p < 4; p++) {
            uint32_t hi, lo; split2(tv[p].x, tv[p].y, hi, lo);
            int boff = ((r0 + (p << 4)) * STR + (jr << 1)) * 2;
            *(uint32_t*)(so + K1_THI + boff) = hi;
            *(uint32_t*)(so + K1_TLO + boff) = lo;
        }
    }
    __syncthreads();

    for (int kb = 0; kb < 128; kb++) {
        const uint32_t sb = smb + (kb & 1) * K1_STAGE;
        const bool more = (kb + 1) < 128;

        // ---- prefetch kb+1 ----
        if (more) {
            const int h = (kb + 1) >> 1, w0 = ((kb + 1) & 1) << 5;
            #pragma unroll
            for (int p = 0; p < 8; p++)
                xv[p] = *(const float2*)&xn[(r0 + (p << 4)) * HWD + h * 64 + w0 + (jr << 1)];
            #pragma unroll
            for (int p = 0; p < 4; p++) {
                int hh = h + tdr[p], ww = w0 + (jr << 1) + tdk[p];
                tv[p] = make_float2(0.f, 0.f);
                if ((unsigned)hh < 64u && (unsigned)ww < 64u)
                    tv[p] = *(const float2*)&xn[tc[p] * HWD + hh * 64 + ww];
            }
        }

        // ---- compute from stage kb&1 ----
        #pragma unroll
        for (int ks = 0; ks < 2; ks++) {
            uint32_t ah[2][4], al[2][4], bh[4][2], bl[4][2];
            #pragma unroll
            for (int tt = 0; tt < 2; tt++) {
                int row = (wc << 5) + (tt << 4) + (lane & 15);
                int col = (ks << 4) + ((lane >> 4) << 3);
                uint32_t off = (uint32_t)(row * STR + col) * 2;
                ldsm4(ah[tt], sb + K1_XHI + off);
                ldsm4(al[tt], sb + K1_XLO + off);
            }
            #pragma unroll
            for (int j = 0; j < 4; j++) {
                int row = (wr << 5) + (j << 3) + (lane & 7);
                int col = (ks << 4) + (((lane >> 3) & 1) << 3);
                uint32_t off = (uint32_t)(row * STR + col) * 2;
                ldsm2(bh[j], sb + K1_THI + off);
                ldsm2(bl[j], sb + K1_TLO + off);
            }
            #pragma unroll
            for (int tt = 0; tt < 2; tt++)
                #pragma unroll
                for (int j = 0; j < 4; j++) {
                    mma_bf16(acc[tt][j], ah[tt], bh[j]);
                    mma_bf16(acc[tt][j], ah[tt], bl[j]);
                    mma_bf16(acc[tt][j], al[tt], bh[j]);
                }
        }

        // ---- convert + STS into the other stage ----
        if (more) {
            char* so = sm + ((kb + 1) & 1) * K1_STAGE;
            #pragma unroll
            for (int p = 0; p < 8; p++) {
                uint32_t hi, lo; split2(xv[p].x, xv[p].y, hi, lo);
                int boff = ((r0 + (p << 4)) * STR + (jr << 1)) * 2;
                *(uint32_t*)(so + K1_XHI + boff) = hi;
                *(uint32_t*)(so + K1_XLO + boff) = lo;
            }
            #pragma unroll
            for (int p = 0; p < 4; p++) {
                uint32_t hi, lo; split2(tv[p].x, tv[p].y, hi, lo);
                int boff = ((r0 + (p << 4)) * STR + (jr << 1)) * 2;
                *(uint32_t*)(so + K1_THI + boff) = hi;
                *(uint32_t*)(so + K1_TLO + boff) = lo;
            }
        }
        __syncthreads();
    }

    // epilogue: t6T[d][m] = p6w[m,d] * acc/64
    const float s1 = 1.0f / 64.0f;
    #pragma unroll
    for (int tt = 0; tt < 2; tt++)
        #pragma unroll
        for (int j = 0; j < 4; j++) {
            int d0 = (wc << 5) + (tt << 4) + (lane >> 2);
            int m  = m0 + (wr << 5) + (j << 3) + ((lane & 3) << 1);
            #pragma unroll
            for (int half = 0; half < 2; half++) {
                int d = d0 + half * 8;
                float v0 = acc[tt][j][half * 2 + 0] * s1 * p6w[m * CCH + d];
                float v1 = acc[tt][j][half * 2 + 1] * s1 * p6w[(m + 1) * CCH + d];
                uint32_t hi, lo; split2(v0, v1, hi, lo);
                size_t o = ((size_t)(n * CCH + d)) * MMK + m;
                *(uint32_t*)&g_t6hi[o] = hi;
                *(uint32_t*)&g_t6lo[o] = lo;
            }
        }
}

// ---------------------------------------------------------------------------
// Kernel 2: out[hw][d] = (1/sqrt(2688)) sum_m t7[m,hw] * t6[m,d]
// CTA: 256 thr, hw(64) x d(128), K=m 2688 (BK=32), double-buffered.
// Warps: wr = hw-half (0/1), wc = d-quarter. T7 staged [m][hw] (stride STR2).
// ---------------------------------------------------------------------------
__global__ __launch_bounds__(256, 2) void k2_proj(const float* __restrict__ x,
                                                  const float* __restrict__ p5w,
                                                  float* __restrict__ out)
{
    extern __shared__ char sm[];
    const uint32_t smb = cvta_sm(sm);

    const int n = blockIdx.y, hw0 = blockIdx.x * 64;
    const int t = threadIdx.x, warp = t >> 5, lane = t & 31;
    const int wr = warp >> 2, wc = warp & 3;
    const float* xn = x + (size_t)n * CCH * HWD;
    const __nv_bfloat16* t6h = g_t6hi + (size_t)n * CCH * MMK;
    const __nv_bfloat16* t6l = g_t6lo + (size_t)n * CCH * MMK;

    float acc[2][4][4] = {};
    // T7 staging: 32 lanes x 2 hw = 64 cols; 8 row-groups
    const int jr2 = t & 31, r2 = t >> 5;
    const int hwg = hw0 + (jr2 << 1);
    const int hq = hwg >> 6, wq = hwg & 63;

    float2 xv[4], pv[4];
    uint4  th[2], tl[2];

    // ---- prefetch kb = 0 ----
    #pragma unroll
    for (int p = 0; p < 4; p++) {
        int m = r2 + (p << 3), c = m / RKT, rk = m - c * RKT;
        int hh = hq + 3 * (rk / 3) - 9, ww = wq + 2 * (rk % 3) - 2;
        xv[p] = make_float2(0.f, 0.f);
        if ((unsigned)hh < 64u && (unsigned)ww < 64u)
            xv[p] = *(const float2*)&xn[c * HWD + hh * 64 + ww];
        pv[p] = *(const float2*)&p5w[(size_t)m * HWD + hwg];
    }
    #pragma unroll
    for (int p = 0; p < 2; p++) {
        int slot = t + (p << 8);
        int d = slot >> 2, ch = slot & 3;
        th[p] = *(const uint4*)((const char*)(t6h + (size_t)d * MMK) + (ch << 4));
        tl[p] = *(const uint4*)((const char*)(t6l + (size_t)d * MMK) + (ch << 4));
    }
    // ---- stage 0 ----
    {
        char* so = sm;
        #pragma unroll
        for (int p = 0; p < 4; p++) {
            uint32_t hi, lo;
            split2((pv[p].x + 1.0f) * xv[p].x, (pv[p].y + 1.0f) * xv[p].y, hi, lo);
            int boff = ((r2 + (p << 3)) * STR2 + (jr2 << 1)) * 2;
            *(uint32_t*)(so + K2_7HI + boff) = hi;
            *(uint32_t*)(so + K2_7LO + boff) = lo;
        }
        #pragma unroll
        for (int p = 0; p < 2; p++) {
            int slot = t + (p << 8);
            int d = slot >> 2, ch = slot & 3;
            *(uint4*)(so + K2_6HI + d * (STR * 2) + (ch << 4)) = th[p];
            *(uint4*)(so + K2_6LO + d * (STR * 2) + (ch << 4)) = tl[p];
        }
    }
    __syncthreads();

    for (int kb = 0; kb < MMK / 32; kb++) {
        const uint32_t sb = smb + (kb & 1) * K2_STAGE;
        const bool more = (kb + 1) < MMK / 32;

        // ---- prefetch kb+1 ----
        if (more) {
            const int mb = (kb + 1) << 5;
            #pragma unroll
            for (int p = 0; p < 4; p++) {
                int m = mb + r2 + (p << 3), c = m / RKT, rk = m - c * RKT;
                int hh = hq + 3 * (rk / 3) - 9, ww = wq + 2 * (rk % 3) - 2;
                xv[p] = make_float2(0.f, 0.f);
                if ((unsigned)hh < 64u && (unsigned)ww < 64u)
                    xv[p] = *(const float2*)&xn[c * HWD + hh * 64 + ww];
                pv[p] = *(const float2*)&p5w[(size_t)m * HWD + hwg];
            }
            #pragma unroll
            for (int p = 0; p < 2; p++) {
                int slot = t + (p << 8);
                int d = slot >> 2, ch = slot & 3;
                th[p] = *(const uint4*)((const char*)(t6h + (size_t)d * MMK + mb) + (ch << 4));
                tl[p] = *(const uint4*)((const char*)(t6l + (size_t)d * MMK + mb) + (ch << 4));
            }
        }

        // ---- compute from stage kb&1 ----
        #pragma unroll
        for (int ks = 0; ks < 2; ks++) {
            uint32_t ah[2][4], al[2][4], bh[4][2], bl[4][2];
            #pragma unroll
            for (int tt = 0; tt < 2; tt++) {   // A via trans: T7 [m][hw]
                int row = (ks << 4) + ((lane >> 4) << 3) + (lane & 7);
                int col = (wr << 5) + (tt << 4) + (((lane >> 3) & 1) << 3);
                uint32_t off = (uint32_t)(row * STR2 + col) * 2;
                ldsm4t(ah[tt], sb + K2_7HI + off);
                ldsm4t(al[tt], sb + K2_7LO + off);
            }
            #pragma unroll
            for (int j = 0; j < 4; j++) {      // B: t6T rows d
                int row = (wc << 5) + (j << 3) + (lane & 7);
                int col = (ks << 4) + (((lane >> 3) & 1) << 3);
                uint32_t off = (uint32_t)(row * STR + col) * 2;
                ldsm2(bh[j], sb + K2_6HI + off);
                ldsm2(bl[j], sb + K2_6LO + off);
            }
            #pragma unroll
            for (int tt = 0; tt < 2; tt++)
                #pragma unroll
                for (int j = 0; j < 4; j++) {
                    mma_bf16(acc[tt][j], ah[tt], bh[j]);
                    mma_bf16(acc[tt][j], ah[tt], bl[j]);
                    mma_bf16(acc[tt][j], al[tt], bh[j]);
                }
        }

        // ---- convert + STS into the other stage ----
        if (more) {
            char* so = sm + ((kb + 1) & 1) * K2_STAGE;
            #pragma unroll
            for (int p = 0; p < 4; p++) {
                uint32_t hi, lo;
                split2((pv[p].x + 1.0f) * xv[p].x, (pv[p].y + 1.0f) * xv[p].y, hi, lo);
                int boff = ((r2 + (p << 3)) * STR2 + (jr2 << 1)) * 2;
                *(uint32_t*)(so + K2_7HI + boff) = hi;
                *(uint32_t*)(so + K2_7LO + boff) = lo;
            }
            #pragma unroll
            for (int p = 0; p < 2; p++) {
                int slot = t + (p << 8);
                int d = slot >> 2, ch = slot & 3;
                *(uint4*)(so + K2_6HI + d * (STR * 2) + (ch << 4)) = th[p];
                *(uint4*)(so + K2_6LO + d * (STR * 2) + (ch << 4)) = tl[p];
            }
        }
        __syncthreads();
    }

    // epilogue: out[(n*C + d)*HW + hw]
    const float s2 = 1.0f / sqrtf((float)MMK);
    #pragma unroll
    for (int tt = 0; tt < 2; tt++)
        #pragma unroll
        for (int j = 0; j < 4; j++) {
            int hwb = hw0 + (wr << 5) + (tt << 4) + (lane >> 2);
            int d   = (wc << 5) + (j << 3) + ((lane & 3) << 1);
            #pragma unroll
            for (int half = 0; half < 2; half++) {
                int hw = hwb + half * 8;
                out[((size_t)(n * CCH + d))     * HWD + hw] = acc[tt][j][half * 2 + 0] * s2;
                out[((size_t)(n * CCH + d + 1)) * HWD + hw] = acc[tt][j][half * 2 + 1] * s2;
            }
        }
}

extern "C" void kernel_launch(void* const* d_in, const int* in_sizes, int n_in,
                              void* d_out, int out_size)
{
    const float* x   = (const float*)d_in[0];   // (4,128,64,64)
    const float* p5w = (const float*)d_in[1];   // (1,128,7,3,64,64)
    const float* p6w = (const float*)d_in[2];   // (1,128,7,3,128)
    float* out = (float*)d_out;                 // (4,128,64,64)

    cudaFuncSetAttribute(k1_corr, cudaFuncAttributeMaxDynamicSharedMemorySize, K1_SMEM);
    cudaFuncSetAttribute(k2_proj, cudaFuncAttributeMaxDynamicSharedMemorySize, K2_SMEM);

    k1_corr<<<dim3(MMK / 64, NBATCH), 256, K1_SMEM>>>(x, p6w);
    k2_proj<<<dim3(HWD / 64, NBATCH), 256, K2_SMEM>>>(x, p5w, out);
}

// round 17
// speedup vs baseline: 5.0931x; 1.1566x over previous
#include <cuda_runtime.h>
#include <cuda_bf16.h>
#include <cstdint>

// Problem constants
#define NBATCH 4
#define CCH 128
#define HWD 4096      // 64*64
#define RKT 21
#define MMK 2688      // 128*21
#define STR 40        // bf16 row stride (80B) for 32-col tiles
#define STR2 72       // bf16 row stride (144B) for 64-col T7 tile (conflict-free)

// t6 stored TRANSPOSED [n][d][m], bf16 hi + lo
__device__ __nv_bfloat16 g_t6hi[(size_t)NBATCH * CCH * MMK];
__device__ __nv_bfloat16 g_t6lo[(size_t)NBATCH * CCH * MMK];
// k1 split-K fp32 partials: [part][n][d][m], 2 x 5.5 MB
__device__ float g_t3p[(size_t)2 * NBATCH * CCH * MMK];

// ---- k1 per-stage smem layout (bytes): X 128xSTR, T 64xSTR --------------
#define K1_XHI 0
#define K1_XLO 10240
#define K1_THI 20480
#define K1_TLO 25600
#define K1_STAGE 30720
#define K1_SMEM (2 * K1_STAGE)    // 61440

// ---- k2 per-stage smem layout: T6 128xSTR, T7 32xSTR2 -------------------
#define K2_6HI 0
#define K2_6LO 10240
#define K2_7HI 20480
#define K2_7LO 25088
#define K2_STAGE 29696
#define K2_SMEM (2 * K2_STAGE)    // 59392

// ---------------- helpers ----------------
static __device__ __forceinline__ uint32_t cvta_sm(const void* p) {
    uint32_t a;
    asm("{ .reg .u64 t; cvta.to.shared.u64 t, %1; cvt.u32.u64 %0, t; }" : "=r"(a) : "l"(p));
    return a;
}
static __device__ __forceinline__ void ldsm4(uint32_t* r, uint32_t a) {
    asm volatile("ldmatrix.sync.aligned.m8n8.x4.shared.b16 {%0,%1,%2,%3}, [%4];"
        : "=r"(r[0]), "=r"(r[1]), "=r"(r[2]), "=r"(r[3]) : "r"(a));
}
static __device__ __forceinline__ void ldsm4t(uint32_t* r, uint32_t a) {
    asm volatile("ldmatrix.sync.aligned.m8n8.x4.trans.shared.b16 {%0,%1,%2,%3}, [%4];"
        : "=r"(r[0]), "=r"(r[1]), "=r"(r[2]), "=r"(r[3]) : "r"(a));
}
static __device__ __forceinline__ void ldsm2(uint32_t* r, uint32_t a) {
    asm volatile("ldmatrix.sync.aligned.m8n8.x2.shared.b16 {%0,%1}, [%2];"
        : "=r"(r[0]), "=r"(r[1]) : "r"(a));
}
static __device__ __forceinline__ void mma_bf16(float* c, const uint32_t* a, const uint32_t* b) {
    asm volatile(
        "mma.sync.aligned.m16n8k16.row.col.f32.bf16.bf16.f32 "
        "{%0,%1,%2,%3}, {%4,%5,%6,%7}, {%8,%9}, {%0,%1,%2,%3};"
        : "+f"(c[0]), "+f"(c[1]), "+f"(c[2]), "+f"(c[3])
        : "r"(a[0]), "r"(a[1]), "r"(a[2]), "r"(a[3]), "r"(b[0]), "r"(b[1]));
}
static __device__ __forceinline__ void split2(float vx, float vy, uint32_t& hi, uint32_t& lo) {
    __nv_bfloat16 hx = __float2bfloat16(vx), hy = __float2bfloat16(vy);
    __nv_bfloat16 lx = __float2bfloat16(vx - __bfloat162float(hx));
    __nv_bfloat16 ly = __float2bfloat16(vy - __bfloat162float(hy));
    hi = (uint32_t)__bfloat16_as_ushort(hx) | ((uint32_t)__bfloat16_as_ushort(hy) << 16);
    lo = (uint32_t)__bfloat16_as_ushort(lx) | ((uint32_t)__bfloat16_as_ushort(ly) << 16);
}

// ---------------------------------------------------------------------------
// Kernel 1 (split-K): t3T_part[d][m] = sum_{hw in half} x[d,hw]*A[m,hw]
// CTA: 256 thr, d(128) x m(64), K-half = 2048 (64 BK-iters), double-buffered.
// grid (42, 2, 4): x = m-tile, y = K-half, z = n. 336 CTAs, balanced.
// ---------------------------------------------------------------------------
__global__ __launch_bounds__(256, 2) void k1_corr(const float* __restrict__ x)
{
    extern __shared__ char sm[];
    const uint32_t smb = cvta_sm(sm);

    const int n = blockIdx.z, yk = blockIdx.y, m0 = blockIdx.x * 64;
    const int k0 = yk * 64;                    // first BK index of this half
    const int t = threadIdx.x, warp = t >> 5, lane = t & 31;
    const int wr = warp >> 2, wc = warp & 3;
    const float* xn = x + (size_t)n * CCH * HWD;

    float acc[2][4][4] = {};
    const int jr = t & 15, r0 = t >> 4;

    // gather geometry for the 4 T-rows this thread stages
    int tc[4], tdr[4], tdk[4];
    #pragma unroll
    for (int p = 0; p < 4; p++) {
        int m = m0 + r0 + (p << 4), c = m / RKT, rk = m - c * RKT;
        tc[p] = c; tdr[p] = 3 * (rk / 3) - 9; tdk[p] = 2 * (rk % 3) - 2;
    }

    float2 xv[8], tv[4];

    // ---- prefetch kb = k0 (k0 even -> w0 = 0, h = k0/2) ----
    {
        const int h = k0 >> 1;
        #pragma unroll
        for (int p = 0; p < 8; p++)
            xv[p] = *(const float2*)&xn[(r0 + (p << 4)) * HWD + h * 64 + (jr << 1)];
        #pragma unroll
        for (int p = 0; p < 4; p++) {
            int hh = h + tdr[p], ww = (jr << 1) + tdk[p];
            tv[p] = make_float2(0.f, 0.f);
            if ((unsigned)hh < 64u && (unsigned)ww < 64u)
                tv[p] = *(const float2*)&xn[tc[p] * HWD + hh * 64 + ww];
        }
    }
    // ---- stage 0 ----
    {
        char* so = sm;
        #pragma unroll
        for (int p = 0; p < 8; p++) {
            uint32_t hi, lo; split2(xv[p].x, xv[p].y, hi, lo);
            int boff = ((r0 + (p << 4)) * STR + (jr << 1)) * 2;
            *(uint32_t*)(so + K1_XHI + boff) = hi;
            *(uint32_t*)(so + K1_XLO + boff) = lo;
        }
        #pragma unroll
        for (int p = 0; p < 4; p++) {
            uint32_t hi, lo; split2(tv[p].x, tv[p].y, hi, lo);
            int boff = ((r0 + (p << 4)) * STR + (jr << 1)) * 2;
            *(uint32_t*)(so + K1_THI + boff) = hi;
            *(uint32_t*)(so + K1_TLO + boff) = lo;
        }
    }
    __syncthreads();

    for (int kb = k0; kb < k0 + 64; kb++) {
        const uint32_t sb = smb + (kb & 1) * K1_STAGE;
        const bool more = (kb + 1) < k0 + 64;

        // ---- prefetch kb+1 ----
        if (more) {
            const int h = (kb + 1) >> 1, w0 = ((kb + 1) & 1) << 5;
            #pragma unroll
            for (int p = 0; p < 8; p++)
                xv[p] = *(const float2*)&xn[(r0 + (p << 4)) * HWD + h * 64 + w0 + (jr << 1)];
            #pragma unroll
            for (int p = 0; p < 4; p++) {
                int hh = h + tdr[p], ww = w0 + (jr << 1) + tdk[p];
                tv[p] = make_float2(0.f, 0.f);
                if ((unsigned)hh < 64u && (unsigned)ww < 64u)
                    tv[p] = *(const float2*)&xn[tc[p] * HWD + hh * 64 + ww];
            }
        }

        // ---- compute from stage kb&1 ----
        #pragma unroll
        for (int ks = 0; ks < 2; ks++) {
            uint32_t ah[2][4], al[2][4], bh[4][2], bl[4][2];
            #pragma unroll
            for (int tt = 0; tt < 2; tt++) {
                int row = (wc << 5) + (tt << 4) + (lane & 15);
                int col = (ks << 4) + ((lane >> 4) << 3);
                uint32_t off = (uint32_t)(row * STR + col) * 2;
                ldsm4(ah[tt], sb + K1_XHI + off);
                ldsm4(al[tt], sb + K1_XLO + off);
            }
            #pragma unroll
            for (int j = 0; j < 4; j++) {
                int row = (wr << 5) + (j << 3) + (lane & 7);
                int col = (ks << 4) + (((lane >> 3) & 1) << 3);
                uint32_t off = (uint32_t)(row * STR + col) * 2;
                ldsm2(bh[j], sb + K1_THI + off);
                ldsm2(bl[j], sb + K1_TLO + off);
            }
            #pragma unroll
            for (int tt = 0; tt < 2; tt++)
                #pragma unroll
                for (int j = 0; j < 4; j++) {
                    mma_bf16(acc[tt][j], ah[tt], bh[j]);
                    mma_bf16(acc[tt][j], ah[tt], bl[j]);
                    mma_bf16(acc[tt][j], al[tt], bh[j]);
                }
        }

        // ---- convert + STS into the other stage ----
        if (more) {
            char* so = sm + ((kb + 1) & 1) * K1_STAGE;
            #pragma unroll
            for (int p = 0; p < 8; p++) {
                uint32_t hi, lo; split2(xv[p].x, xv[p].y, hi, lo);
                int boff = ((r0 + (p << 4)) * STR + (jr << 1)) * 2;
                *(uint32_t*)(so + K1_XHI + boff) = hi;
                *(uint32_t*)(so + K1_XLO + boff) = lo;
            }
            #pragma unroll
            for (int p = 0; p < 4; p++) {
                uint32_t hi, lo; split2(tv[p].x, tv[p].y, hi, lo);
                int boff = ((r0 + (p << 4)) * STR + (jr << 1)) * 2;
                *(uint32_t*)(so + K1_THI + boff) = hi;
                *(uint32_t*)(so + K1_TLO + boff) = lo;
            }
        }
        __syncthreads();
    }

    // epilogue: write fp32 partials to g_t3p[yk][n][d][m] (float2 along m)
    float* dst = g_t3p + ((size_t)(yk * NBATCH + n)) * CCH * MMK;
    #pragma unroll
    for (int tt = 0; tt < 2; tt++)
        #pragma unroll
        for (int j = 0; j < 4; j++) {
            int d0 = (wc << 5) + (tt << 4) + (lane >> 2);
            int m  = m0 + (wr << 5) + (j << 3) + ((lane & 3) << 1);
            #pragma unroll
            for (int half = 0; half < 2; half++) {
                int d = d0 + half * 8;
                float2 v = make_float2(acc[tt][j][half * 2 + 0], acc[tt][j][half * 2 + 1]);
                *(float2*)&dst[(size_t)d * MMK + m] = v;
            }
        }
}

// ---------------------------------------------------------------------------
// Kernel 1b (reduce): t6T[n][d][m] = split( p6w[m,d] * (t3a+t3b)/64 )
// block 256, grid (21 m-blocks, 8 d-blocks, 4 n). p6w transposed via smem.
// ---------------------------------------------------------------------------
__global__ __launch_bounds__(256) void k1b_reduce(const float* __restrict__ p6w)
{
    __shared__ float pw[16][130];
    const int mb = blockIdx.x * 128, db = blockIdx.y * 16, n = blockIdx.z;
    const int t = threadIdx.x;

    // load p6w[m 128][d 16] -> pw[d][m], coalesced over d
    {
        const int d_l = t & 15, m_l0 = t >> 4;
        #pragma unroll
        for (int p = 0; p < 8; p++) {
            int m_l = m_l0 + p * 16;
            pw[d_l][m_l] = p6w[(size_t)(mb + m_l) * CCH + db + d_l];
        }
    }
    __syncthreads();

    const int ml = (t & 63) << 1;    // local m (even), float2 lane
    const int dr = t >> 6;           // 0..3
    const float s1 = 1.0f / 64.0f;
    const float* t3a = g_t3p + ((size_t)(0 * NBATCH + n)) * CCH * MMK;
    const float* t3b = g_t3p + ((size_t)(1 * NBATCH + n)) * CCH * MMK;

    #pragma unroll
    for (int dd = 0; dd < 4; dd++) {
        int d_l = dr + (dd << 2);
        int d = db + d_l;
        size_t src = (size_t)d * MMK + mb + ml;
        float2 a = *(const float2*)&t3a[src];
        float2 b = *(const float2*)&t3b[src];
        float v0 = (a.x + b.x) * s1 * pw[d_l][ml];
        float v1 = (a.y + b.y) * s1 * pw[d_l][ml + 1];
        uint32_t hi, lo; split2(v0, v1, hi, lo);
        size_t o = ((size_t)(n * CCH + d)) * MMK + mb + ml;
        *(uint32_t*)&g_t6hi[o] = hi;
        *(uint32_t*)&g_t6lo[o] = lo;
    }
}

// ---------------------------------------------------------------------------
// Kernel 2: out[hw][d] = (1/sqrt(2688)) sum_m t7[m,hw] * t6[m,d]
// CTA: 256 thr, hw(64) x d(128), K=m 2688 (BK=32), double-buffered. UNCHANGED.
// ---------------------------------------------------------------------------
__global__ __launch_bounds__(256, 2) void k2_proj(const float* __restrict__ x,
                                                  const float* __restrict__ p5w,
                                                  float* __restrict__ out)
{
    extern __shared__ char sm[];
    const uint32_t smb = cvta_sm(sm);

    const int n = blockIdx.y, hw0 = blockIdx.x * 64;
    const int t = threadIdx.x, warp = t >> 5, lane = t & 31;
    const int wr = warp >> 2, wc = warp & 3;
    const float* xn = x + (size_t)n * CCH * HWD;
    const __nv_bfloat16* t6h = g_t6hi + (size_t)n * CCH * MMK;
    const __nv_bfloat16* t6l = g_t6lo + (size_t)n * CCH * MMK;

    float acc[2][4][4] = {};
    const int jr2 = t & 31, r2 = t >> 5;
    const int hwg = hw0 + (jr2 << 1);
    const int hq = hwg >> 6, wq = hwg & 63;

    float2 xv[4], pv[4];
    uint4  th[2], tl[2];

    // ---- prefetch kb = 0 ----
    #pragma unroll
    for (int p = 0; p < 4; p++) {
        int m = r2 + (p << 3), c = m / RKT, rk = m - c * RKT;
        int hh = hq + 3 * (rk / 3) - 9, ww = wq + 2 * (rk % 3) - 2;
        xv[p] = make_float2(0.f, 0.f);
        if ((unsigned)hh < 64u && (unsigned)ww < 64u)
            xv[p] = *(const float2*)&xn[c * HWD + hh * 64 + ww];
        pv[p] = *(const float2*)&p5w[(size_t)m * HWD + hwg];
    }
    #pragma unroll
    for (int p = 0; p < 2; p++) {
        int slot = t + (p << 8);
        int d = slot >> 2, ch = slot & 3;
        th[p] = *(const uint4*)((const char*)(t6h + (size_t)d * MMK) + (ch << 4));
        tl[p] = *(const uint4*)((const char*)(t6l + (size_t)d * MMK) + (ch << 4));
    }
    // ---- stage 0 ----
    {
        char* so = sm;
        #pragma unroll
        for (int p = 0; p < 4; p++) {
            uint32_t hi, lo;
            split2((pv[p].x + 1.0f) * xv[p].x, (pv[p].y + 1.0f) * xv[p].y, hi, lo);
            int boff = ((r2 + (p << 3)) * STR2 + (jr2 << 1)) * 2;
            *(uint32_t*)(so + K2_7HI + boff) = hi;
            *(uint32_t*)(so + K2_7LO + boff) = lo;
        }
        #pragma unroll
        for (int p = 0; p < 2; p++) {
            int slot = t + (p << 8);
            int d = slot >> 2, ch = slot & 3;
            *(uint4*)(so + K2_6HI + d * (STR * 2) + (ch << 4)) = th[p];
            *(uint4*)(so + K2_6LO + d * (STR * 2) + (ch << 4)) = tl[p];
        }
    }
    __syncthreads();

    for (int kb = 0; kb < MMK / 32; kb++) {
        const uint32_t sb = smb + (kb & 1) * K2_STAGE;
        const bool more = (kb + 1) < MMK / 32;

        // ---- prefetch kb+1 ----
        if (more) {
            const int mb = (kb + 1) << 5;
            #pragma unroll
            for (int p = 0; p < 4; p++) {
                int m = mb + r2 + (p << 3), c = m / RKT, rk = m - c * RKT;
                int hh = hq + 3 * (rk / 3) - 9, ww = wq + 2 * (rk % 3) - 2;
                xv[p] = make_float2(0.f, 0.f);
                if ((unsigned)hh < 64u && (unsigned)ww < 64u)
                    xv[p] = *(const float2*)&xn[c * HWD + hh * 64 + ww];
                pv[p] = *(const float2*)&p5w[(size_t)m * HWD + hwg];
            }
            #pragma unroll
            for (int p = 0; p < 2; p++) {
                int slot = t + (p << 8);
                int d = slot >> 2, ch = slot & 3;
                th[p] = *(const uint4*)((const char*)(t6h + (size_t)d * MMK + mb) + (ch << 4));
                tl[p] = *(const uint4*)((const char*)(t6l + (size_t)d * MMK + mb) + (ch << 4));
            }
        }

        // ---- compute from stage kb&1 ----
        #pragma unroll
        for (int ks = 0; ks < 2; ks++) {
            uint32_t ah[2][4], al[2][4], bh[4][2], bl[4][2];
            #pragma unroll
            for (int tt = 0; tt < 2; tt++) {   // A via trans: T7 [m][hw]
                int row = (ks << 4) + ((lane >> 4) << 3) + (lane & 7);
                int col = (wr << 5) + (tt << 4) + (((lane >> 3) & 1) << 3);
                uint32_t off = (uint32_t)(row * STR2 + col) * 2;
                ldsm4t(ah[tt], sb + K2_7HI + off);
                ldsm4t(al[tt], sb + K2_7LO + off);
            }
            #pragma unroll
            for (int j = 0; j < 4; j++) {      // B: t6T rows d
                int row = (wc << 5) + (j << 3) + (lane & 7);
                int col = (ks << 4) + (((lane >> 3) & 1) << 3);
                uint32_t off = (uint32_t)(row * STR + col) * 2;
                ldsm2(bh[j], sb + K2_6HI + off);
                ldsm2(bl[j], sb + K2_6LO + off);
            }
            #pragma unroll
            for (int tt = 0; tt < 2; tt++)
                #pragma unroll
                for (int j = 0; j < 4; j++) {
                    mma_bf16(acc[tt][j], ah[tt], bh[j]);
                    mma_bf16(acc[tt][j], ah[tt], bl[j]);
                    mma_bf16(acc[tt][j], al[tt], bh[j]);
                }
        }

        // ---- convert + STS into the other stage ----
        if (more) {
            char* so = sm + ((kb + 1) & 1) * K2_STAGE;
            #pragma unroll
            for (int p = 0; p < 4; p++) {
                uint32_t hi, lo;
                split2((pv[p].x + 1.0f) * xv[p].x, (pv[p].y + 1.0f) * xv[p].y, hi, lo);
                int boff = ((r2 + (p << 3)) * STR2 + (jr2 << 1)) * 2;
                *(uint32_t*)(so + K2_7HI + boff) = hi;
                *(uint32_t*)(so + K2_7LO + boff) = lo;
            }
            #pragma unroll
            for (int p = 0; p < 2; p++) {
                int slot = t + (p << 8);
                int d = slot >> 2, ch = slot & 3;
                *(uint4*)(so + K2_6HI + d * (STR * 2) + (ch << 4)) = th[p];
                *(uint4*)(so + K2_6LO + d * (STR * 2) + (ch << 4)) = tl[p];
            }
        }
        __syncthreads();
    }

    // epilogue: out[(n*C + d)*HW + hw]
    const float s2 = 1.0f / sqrtf((float)MMK);
    #pragma unroll
    for (int tt = 0; tt < 2; tt++)
        #pragma unroll
        for (int j = 0; j < 4; j++) {
            int hwb = hw0 + (wr << 5) + (tt << 4) + (lane >> 2);
            int d   = (wc << 5) + (j << 3) + ((lane & 3) << 1);
            #pragma unroll
            for (int half = 0; half < 2; half++) {
                int hw = hwb + half * 8;
                out[((size_t)(n * CCH + d))     * HWD + hw] = acc[tt][j][half * 2 + 0] * s2;
                out[((size_t)(n * CCH + d + 1)) * HWD + hw] = acc[tt][j][half * 2 + 1] * s2;
            }
        }
}

extern "C" void kernel_launch(void* const* d_in, const int* in_sizes, int n_in,
                              void* d_out, int out_size)
{
    const float* x   = (const float*)d_in[0];   // (4,128,64,64)
    const float* p5w = (const float*)d_in[1];   // (1,128,7,3,64,64)
    const float* p6w = (const float*)d_in[2];   // (1,128,7,3,128)
    float* out = (float*)d_out;                 // (4,128,64,64)

    cudaFuncSetAttribute(k1_corr, cudaFuncAttributeMaxDynamicSharedMemorySize, K1_SMEM);
    cudaFuncSetAttribute(k2_proj, cudaFuncAttributeMaxDynamicSharedMemorySize, K2_SMEM);

    k1_corr<<<dim3(MMK / 64, 2, NBATCH), 256, K1_SMEM>>>(x);
    k1b_reduce<<<dim3(MMK / 128, CCH / 16, NBATCH), 256>>>(p6w);
    k2_proj<<<dim3(HWD / 64, NBATCH), 256, K2_SMEM>>>(x, p5w, out);
}